// round 4
// baseline (speedup 1.0000x reference)
#include <cuda_runtime.h>
#include <cuda_bf16.h>
#include <cstdint>
#include <cstddef>

#define BATCH 4
#define CDIM  512
#define KDIM  64
#define NDIM  4096
#define NN    ((size_t)NDIM * NDIM)

// ---------------- device scratch (no allocs allowed) ----------------
// NOTE: f/g operand arrays are stored PRE-SWIZZLED (XOR-16B within each
// 128-row x 64-col tile) so attention can bulk-copy them linearly.
__device__ __align__(128) __nv_bfloat16 d_fa_hi[BATCH * NDIM * KDIM]; // f, i-major
__device__ __align__(128) __nv_bfloat16 d_fa_lo[BATCH * NDIM * KDIM];
__device__ __align__(128) __nv_bfloat16 d_gb_hi[BATCH * NDIM * KDIM]; // g, j-major
__device__ __align__(128) __nv_bfloat16 d_gb_lo[BATCH * NDIM * KDIM];
__device__ __align__(16) __nv_bfloat16 d_w_hi[128 * CDIM];            // [Wq;Wk] split
__device__ __align__(16) __nv_bfloat16 d_w_lo[128 * CDIM];
__device__ float d_rowsum[BATCH * NDIM];  // row sums of beta
__device__ float d_y[BATCH * CDIM];
__device__ float d_xbar[BATCH * CDIM];

__device__ __forceinline__ float fast_exp(float x) {
    float y;
    asm("ex2.approx.ftz.f32 %0, %1;" : "=f"(y) : "f"(x * 1.4426950408889634f));
    return y;
}

__device__ __forceinline__ float warp_sum(float v) {
    #pragma unroll
    for (int o = 16; o; o >>= 1) v += __shfl_xor_sync(0xFFFFFFFFu, v, o);
    return v;
}

__device__ __forceinline__ uint32_t smem_u32(const void* p) {
    uint32_t a;
    asm("{ .reg .u64 t; cvta.to.shared.u64 t, %1; cvt.u32.u64 %0, t; }"
        : "=r"(a) : "l"(p));
    return a;
}

// A fragment (m16 x k16) via ldmatrix x4 from m-major SW-swizzled [128][64] bf16 tile
__device__ __forceinline__ void ldA(uint32_t tile, int rbase, int kc, int lane, uint32_t* a) {
    int r = rbase + (lane & 15);
    int c = kc + (lane >> 4);
    uint32_t addr = tile + r * 128 + ((c ^ (r & 7)) << 4);
    asm volatile("ldmatrix.sync.aligned.m8n8.x4.shared.b16 {%0,%1,%2,%3}, [%4];"
                 : "=r"(a[0]), "=r"(a[1]), "=r"(a[2]), "=r"(a[3]) : "r"(addr));
}

// B fragment (n8 x k16) via ldmatrix x2
__device__ __forceinline__ void ldB(uint32_t tile, int rbase, int kc, int lane, uint32_t* bb) {
    int r = rbase + (lane & 7);
    int c = kc + ((lane >> 3) & 1);
    uint32_t addr = tile + r * 128 + ((c ^ (r & 7)) << 4);
    asm volatile("ldmatrix.sync.aligned.m8n8.x2.shared.b16 {%0,%1}, [%2];"
                 : "=r"(bb[0]), "=r"(bb[1]) : "r"(addr));
}

__device__ __forceinline__ void mma_bf16(float* acc, const uint32_t* a, const uint32_t* bb) {
    asm volatile(
        "mma.sync.aligned.m16n8k16.row.col.f32.bf16.bf16.f32 "
        "{%0,%1,%2,%3}, {%4,%5,%6,%7}, {%8,%9}, {%0,%1,%2,%3};"
        : "+f"(acc[0]), "+f"(acc[1]), "+f"(acc[2]), "+f"(acc[3])
        : "r"(a[0]), "r"(a[1]), "r"(a[2]), "r"(a[3]), "r"(bb[0]), "r"(bb[1]));
}

// ---------------- mbarrier + bulk-copy helpers (sm_90 baseline PTX) ----------------
#define MBARRIER_INIT(mbar, count) \
    asm volatile("mbarrier.init.shared.b64 [%0], %1;" \
                 :: "r"((uint32_t)(mbar)), "r"((uint32_t)(count)) : "memory")
#define MBARRIER_EXPECT_TX(mbar, bytes) \
    asm volatile("mbarrier.arrive.expect_tx.shared.b64 _, [%0], %1;" \
                 :: "r"((uint32_t)(mbar)), "r"((uint32_t)(bytes)) : "memory")
#define FENCE_PROXY_ASYNC() \
    asm volatile("fence.proxy.async.shared::cta;" ::: "memory")
#define CP_BULK(dst_smem, src_gmem, bytes, mbar) \
    asm volatile("cp.async.bulk.shared::cta.global.mbarrier::complete_tx::bytes " \
                 "[%0], [%1], %2, [%3];" \
                 :: "r"((uint32_t)(dst_smem)), "l"(src_gmem), "r"((uint32_t)(bytes)), \
                    "r"((uint32_t)(mbar)) : "memory")

__device__ __forceinline__ void mbar_wait_parity(uint32_t mbar, uint32_t parity) {
    uint32_t done;
    asm volatile(
        "{\n\t.reg .pred p;\n\t"
        "mbarrier.try_wait.parity.acquire.cta.shared::cta.b64 p, [%1], %2;\n\t"
        "selp.b32 %0, 1, 0, p;\n\t}"
        : "=r"(done) : "r"(mbar), "r"(parity) : "memory");
    if (!done) {
        asm volatile(
            "{\n\t.reg .pred P1;\n\t"
            "WAIT_LOOP_%=:\n\t"
            "mbarrier.try_wait.parity.acquire.cta.shared::cta.b64 P1, [%0], %1, 0x989680;\n\t"
            "@P1 bra.uni WAIT_DONE_%=;\n\t"
            "bra.uni WAIT_LOOP_%=;\n\t"
            "WAIT_DONE_%=:\n\t}"
            :: "r"(mbar), "r"(parity) : "memory");
    }
}

// ---------------- zero rowsum accumulator ----------------
__global__ void zero_kernel() {
    int i = blockIdx.x * blockDim.x + threadIdx.x;
    if (i < BATCH * NDIM) d_rowsum[i] = 0.f;
}

// ---------------- W split prep: [Wq;Wk] fp32 -> bf16 hi/lo ----------------
__global__ __launch_bounds__(256) void wsplit_kernel(const float* __restrict__ Wq,
                                                     const float* __restrict__ Wk) {
    int idx = blockIdx.x * blockDim.x + threadIdx.x;
    if (idx >= 128 * CDIM) return;
    int m = idx >> 9;
    int c = idx & 511;
    float w = (m < 64) ? Wq[m * CDIM + c] : Wk[(m - 64) * CDIM + c];
    __nv_bfloat16 hi = __float2bfloat16(w);
    d_w_hi[idx] = hi;
    d_w_lo[idx] = __float2bfloat16(w - __bfloat162float(hi));
}

// ---------------- FG: [f;g] = [Wq;Wk] @ x[b] via bf16x3 mma.sync ----------------
#define FG_SMEM (128 * 132 * 4)  // 67584

__global__ __launch_bounds__(256) void fg_kernel(const float* __restrict__ x) {
    extern __shared__ __align__(1024) char dynsm[];
    uint32_t smem_base = smem_u32(dynsm);
    uint4* sWhi = (uint4*)(dynsm);
    uint4* sWlo = (uint4*)(dynsm + 16384);
    uint4* sXhi = (uint4*)(dynsm + 32768);
    uint4* sXlo = (uint4*)(dynsm + 49152);
    float* S = (float*)dynsm;  // [128][132] alias after mainloop

    int b = blockIdx.y;
    int i0 = blockIdx.x * 128;
    int tid = threadIdx.x;
    int lane = tid & 31, wid = tid >> 5;
    int wm = wid >> 2, wn = wid & 3;
    const float* xb = x + (size_t)b * CDIM * NDIM;

    float acc[4][4][4];
    #pragma unroll
    for (int mf = 0; mf < 4; mf++)
        #pragma unroll
        for (int nf = 0; nf < 4; nf++)
            #pragma unroll
            for (int e = 0; e < 4; e++) acc[mf][nf][e] = 0.f;

    for (int c0 = 0; c0 < CDIM; c0 += 64) {
        #pragma unroll
        for (int t = 0; t < 4; t++) {
            int idx = tid + t * 256;
            int m = idx >> 3, ch = idx & 7;
            int soff = m * 8 + (ch ^ (m & 7));
            sWhi[soff] = ((const uint4*)(d_w_hi + (size_t)m * CDIM + c0))[ch];
            sWlo[soff] = ((const uint4*)(d_w_lo + (size_t)m * CDIM + c0))[ch];
        }
        #pragma unroll
        for (int t = 0; t < 4; t++) {
            int idx = tid + t * 256;
            int n = idx & 127, oct = idx >> 7;
            const float* src = xb + (size_t)(c0 + oct * 8) * NDIM + i0 + n;
            __align__(16) __nv_bfloat16 h8[8], l8[8];
            #pragma unroll
            for (int j = 0; j < 8; j++) {
                float v = src[(size_t)j * NDIM];
                __nv_bfloat16 hi = __float2bfloat16(v);
                h8[j] = hi;
                l8[j] = __float2bfloat16(v - __bfloat162float(hi));
            }
            int soff = n * 8 + (oct ^ (n & 7));
            sXhi[soff] = *(uint4*)h8;
            sXlo[soff] = *(uint4*)l8;
        }
        __syncthreads();

        uint32_t tA = smem_base, tAlo = smem_base + 16384;
        uint32_t tB = smem_base + 32768, tBlo = smem_base + 49152;
        #pragma unroll
        for (int ks = 0; ks < 4; ks++) {
            int kc = ks * 2;
            uint32_t ahi[4][4], alo[4][4], bhi[4][2], blo[4][2];
            #pragma unroll
            for (int mf = 0; mf < 4; mf++) ldA(tA, wm * 64 + mf * 16, kc, lane, ahi[mf]);
            #pragma unroll
            for (int nf = 0; nf < 4; nf++) ldB(tB, wn * 32 + nf * 8, kc, lane, bhi[nf]);
            #pragma unroll
            for (int mf = 0; mf < 4; mf++)
                #pragma unroll
                for (int nf = 0; nf < 4; nf++) mma_bf16(acc[mf][nf], ahi[mf], bhi[nf]);
            #pragma unroll
            for (int mf = 0; mf < 4; mf++) ldA(tAlo, wm * 64 + mf * 16, kc, lane, alo[mf]);
            #pragma unroll
            for (int mf = 0; mf < 4; mf++)
                #pragma unroll
                for (int nf = 0; nf < 4; nf++) mma_bf16(acc[mf][nf], alo[mf], bhi[nf]);
            #pragma unroll
            for (int nf = 0; nf < 4; nf++) ldB(tBlo, wn * 32 + nf * 8, kc, lane, blo[nf]);
            #pragma unroll
            for (int mf = 0; mf < 4; mf++)
                #pragma unroll
                for (int nf = 0; nf < 4; nf++) mma_bf16(acc[mf][nf], ahi[mf], blo[nf]);
        }
        __syncthreads();
    }

    #pragma unroll
    for (int mf = 0; mf < 4; mf++)
        #pragma unroll
        for (int nf = 0; nf < 4; nf++) {
            int r = wm * 64 + mf * 16 + (lane >> 2);
            int cc = wn * 32 + nf * 8 + (lane & 3) * 2;
            S[r * 132 + cc]           = acc[mf][nf][0];
            S[r * 132 + cc + 1]       = acc[mf][nf][1];
            S[(r + 8) * 132 + cc]     = acc[mf][nf][2];
            S[(r + 8) * 132 + cc + 1] = acc[mf][nf][3];
        }
    __syncthreads();

    // write split bf16 PRE-SWIZZLED: chunk index XORed with (row & 7)
    int arr = lane >> 3, chunk = lane & 7;
    int mbase = (arr >= 2 ? 64 : 0) + chunk * 8;
    __nv_bfloat16* dst = (arr == 0) ? d_fa_hi : (arr == 1) ? d_fa_lo
                       : (arr == 2) ? d_gb_hi : d_gb_lo;
    for (int r = wid; r < 128; r += 8) {
        __align__(16) __nv_bfloat16 vals[8];
        #pragma unroll
        for (int e = 0; e < 8; e++) {
            float v = S[(mbase + e) * 132 + r];
            __nv_bfloat16 hi = __float2bfloat16(v);
            if (arr & 1) vals[e] = __float2bfloat16(v - __bfloat162float(hi));
            else         vals[e] = hi;
        }
        int chs = chunk ^ (r & 7);
        *(uint4*)(dst + ((size_t)b * NDIM + i0 + r) * KDIM + chs * 8) = *(uint4*)vals;
    }
}

// ---------------- fused attention: one CTA per (b, 128-j strip) ----------------
// Phase 1 (i-tiles 0..31): accumulate Z[j] in registers.
// Phase 2 (i-tiles 0..31): recompute, write beta = exp(s)/Z, accumulate rowsum.
// B (g) tiles resident in smem; A (f) tiles stream via 2-stage cp.async.bulk ring.
// SMEM map: [0,32K) B hi/lo; [32K,96K) A ring (2 x 32K); sZ @98304; zbuf @98816;
//           mbars @99840.
#define ATTN_SMEM 100352

__global__ __launch_bounds__(256, 1) void attn_fused_kernel(float* __restrict__ beta_out) {
    extern __shared__ __align__(1024) char dynsm[];
    uint32_t smem_base = smem_u32(dynsm);
    const uint32_t SB  = smem_base;             // B hi @0, lo @16384
    const uint32_t SA0 = smem_base + 32768;     // ring stage s at +s*32768
    float* sZ   = (float*)(dynsm + 98304);      // 128 floats
    float* zbuf = (float*)(dynsm + 98816);      // 2 x 128 floats
    const uint32_t MB_FULL0 = smem_base + 99840;
    const uint32_t MB_FULL1 = smem_base + 99848;
    const uint32_t MB_B     = smem_base + 99856;

    int b  = blockIdx.y;
    int j0 = blockIdx.x * 128;
    int tid = threadIdx.x;
    int lane = tid & 31, wid = tid >> 5;
    int wm = wid >> 2, wn = wid & 3;

    const char* gBhi = (const char*)(d_gb_hi + ((size_t)b * NDIM + j0) * KDIM);
    const char* gBlo = (const char*)(d_gb_lo + ((size_t)b * NDIM + j0) * KDIM);
    const char* gAhi = (const char*)(d_fa_hi + (size_t)b * NDIM * KDIM);
    const char* gAlo = (const char*)(d_fa_lo + (size_t)b * NDIM * KDIM);

    if (tid == 0) {
        MBARRIER_INIT(MB_FULL0, 1);
        MBARRIER_INIT(MB_FULL1, 1);
        MBARRIER_INIT(MB_B, 1);
        FENCE_PROXY_ASYNC();
        MBARRIER_EXPECT_TX(MB_B, 32768);
        CP_BULK(SB,         gBhi, 16384, MB_B);
        CP_BULK(SB + 16384, gBlo, 16384, MB_B);
        MBARRIER_EXPECT_TX(MB_FULL0, 32768);
        CP_BULK(SA0,         gAhi, 16384, MB_FULL0);
        CP_BULK(SA0 + 16384, gAlo, 16384, MB_FULL0);
        MBARRIER_EXPECT_TX(MB_FULL1, 32768);
        CP_BULK(SA0 + 32768, gAhi + 16384, 16384, MB_FULL1);
        CP_BULK(SA0 + 49152, gAlo + 16384, 16384, MB_FULL1);
    }
    __syncthreads();
    mbar_wait_parity(MB_B, 0);

    uint32_t tB = SB, tBlo = SB + 16384;
    float zp0[4] = {0.f, 0.f, 0.f, 0.f};
    float zp1[4] = {0.f, 0.f, 0.f, 0.f};
    float* ob = beta_out + (size_t)b * NN;

    for (int n = 0; n < 64; n++) {
        int s = n & 1;
        uint32_t mb = s ? MB_FULL1 : MB_FULL0;
        mbar_wait_parity(mb, (n >> 1) & 1);

        uint32_t tA = SA0 + s * 32768, tAlo = tA + 16384;
        float acc[4][4][4];
        #pragma unroll
        for (int mf = 0; mf < 4; mf++)
            #pragma unroll
            for (int nf = 0; nf < 4; nf++)
                #pragma unroll
                for (int e = 0; e < 4; e++) acc[mf][nf][e] = 0.f;

        #pragma unroll
        for (int ks = 0; ks < 4; ks++) {
            int kc = ks * 2;
            uint32_t ahi[4][4], alo[4][4], bhi[4][2], blo[4][2];
            #pragma unroll
            for (int mf = 0; mf < 4; mf++) ldA(tA, wm * 64 + mf * 16, kc, lane, ahi[mf]);
            #pragma unroll
            for (int nf = 0; nf < 4; nf++) ldB(tB, wn * 32 + nf * 8, kc, lane, bhi[nf]);
            #pragma unroll
            for (int mf = 0; mf < 4; mf++)
                #pragma unroll
                for (int nf = 0; nf < 4; nf++) mma_bf16(acc[mf][nf], ahi[mf], bhi[nf]);
            #pragma unroll
            for (int mf = 0; mf < 4; mf++) ldA(tAlo, wm * 64 + mf * 16, kc, lane, alo[mf]);
            #pragma unroll
            for (int mf = 0; mf < 4; mf++)
                #pragma unroll
                for (int nf = 0; nf < 4; nf++) mma_bf16(acc[mf][nf], alo[mf], bhi[nf]);
            #pragma unroll
            for (int nf = 0; nf < 4; nf++) ldB(tBlo, wn * 32 + nf * 8, kc, lane, blo[nf]);
            #pragma unroll
            for (int mf = 0; mf < 4; mf++)
                #pragma unroll
                for (int nf = 0; nf < 4; nf++) mma_bf16(acc[mf][nf], ahi[mf], blo[nf]);
        }
        __syncthreads();  // all warps done reading ring stage s

        if (tid == 0 && n < 62) {
            size_t t = (size_t)((n + 2) & 31) * 16384;
            MBARRIER_EXPECT_TX(mb, 32768);
            CP_BULK(tA,   gAhi + t, 16384, mb);
            CP_BULK(tAlo, gAlo + t, 16384, mb);
        }

        if (n < 32) {
            // phase 1: lane-local Z partials (no shuffles in the loop)
            #pragma unroll
            for (int nf = 0; nf < 4; nf++) {
                float s0 = 0.f, s1 = 0.f;
                #pragma unroll
                for (int mf = 0; mf < 4; mf++) {
                    s0 += fast_exp(acc[mf][nf][0]) + fast_exp(acc[mf][nf][2]);
                    s1 += fast_exp(acc[mf][nf][1]) + fast_exp(acc[mf][nf][3]);
                }
                zp0[nf] += s0;
                zp1[nf] += s1;
            }
            if (n == 31) {
                // finalize Z: butterfly over the 8 row-groups, merge wm halves
                #pragma unroll
                for (int nf = 0; nf < 4; nf++) {
                    #pragma unroll
                    for (int o = 4; o < 32; o <<= 1) {
                        zp0[nf] += __shfl_xor_sync(0xFFFFFFFFu, zp0[nf], o);
                        zp1[nf] += __shfl_xor_sync(0xFFFFFFFFu, zp1[nf], o);
                    }
                }
                if (lane < 4) {
                    #pragma unroll
                    for (int nf = 0; nf < 4; nf++) {
                        int cc = wn * 32 + nf * 8 + lane * 2;
                        zbuf[wm * 128 + cc]     = zp0[nf];
                        zbuf[wm * 128 + cc + 1] = zp1[nf];
                    }
                }
                __syncthreads();
                if (tid < 128) sZ[tid] = 1.0f / (zbuf[tid] + zbuf[128 + tid]);
                __syncthreads();
            }
        } else {
            // phase 2: beta = exp(s)/Z, accumulate rowsum
            int i0 = (n - 32) * 128;
            float rs0[4], rs1[4];
            #pragma unroll
            for (int mf = 0; mf < 4; mf++) { rs0[mf] = 0.f; rs1[mf] = 0.f; }
            #pragma unroll
            for (int mf = 0; mf < 4; mf++) {
                int r = wm * 64 + mf * 16 + (lane >> 2);
                #pragma unroll
                for (int nf = 0; nf < 4; nf++) {
                    int cc = wn * 32 + nf * 8 + (lane & 3) * 2;
                    float iz0 = sZ[cc], iz1 = sZ[cc + 1];
                    float v0 = fast_exp(acc[mf][nf][0]) * iz0;
                    float v1 = fast_exp(acc[mf][nf][1]) * iz1;
                    float v2 = fast_exp(acc[mf][nf][2]) * iz0;
                    float v3 = fast_exp(acc[mf][nf][3]) * iz1;
                    *(float2*)(ob + (size_t)(i0 + r) * NDIM + j0 + cc)     = make_float2(v0, v1);
                    *(float2*)(ob + (size_t)(i0 + r + 8) * NDIM + j0 + cc) = make_float2(v2, v3);
                    rs0[mf] += v0 + v1;
                    rs1[mf] += v2 + v3;
                }
            }
            #pragma unroll
            for (int mf = 0; mf < 4; mf++) {
                #pragma unroll
                for (int o = 1; o < 4; o <<= 1) {
                    rs0[mf] += __shfl_xor_sync(0xFFFFFFFFu, rs0[mf], o);
                    rs1[mf] += __shfl_xor_sync(0xFFFFFFFFu, rs1[mf], o);
                }
            }
            if ((lane & 3) == 0) {
                #pragma unroll
                for (int mf = 0; mf < 4; mf++) {
                    int r = wm * 64 + mf * 16 + (lane >> 2);
                    atomicAdd(&d_rowsum[b * NDIM + i0 + r], rs0[mf]);
                    atomicAdd(&d_rowsum[b * NDIM + i0 + r + 8], rs1[mf]);
                }
            }
        }
    }
}

// ---------------- pooled epilogue ----------------
__global__ __launch_bounds__(256) void pool1_kernel(const float* __restrict__ x) {
    int b = blockIdx.y;
    int cc = blockIdx.x * 8 + (threadIdx.x >> 5);
    int lane = threadIdx.x & 31;
    const float* xr = x + ((size_t)b * CDIM + cc) * NDIM;
    const float* rs = d_rowsum + b * NDIM;
    float ay = 0.f, ax = 0.f;
    for (int i = lane; i < NDIM; i += 32) {
        float xv = xr[i];
        ay += xv * rs[i];
        ax += xv;
    }
    ay = warp_sum(ay); ax = warp_sum(ax);
    if (lane == 0) {
        d_y[b * CDIM + cc]    = ay * (1.0f / NDIM);
        d_xbar[b * CDIM + cc] = ax * (1.0f / NDIM);
    }
}

__global__ __launch_bounds__(256) void pool2_kernel(const float* __restrict__ Wv,
                                                    const float* __restrict__ gamma,
                                                    float* __restrict__ out) {
    int b = blockIdx.y;
    int c = blockIdx.x * 8 + (threadIdx.x >> 5);
    int lane = threadIdx.x & 31;
    const float* wr = Wv + (size_t)c * CDIM;
    const float* yb = d_y + b * CDIM;
    float a = 0.f;
    for (int k = lane; k < CDIM; k += 32) a += wr[k] * yb[k];
    a = warp_sum(a);
    if (lane == 0) out[b * CDIM + c] = gamma[0] * a + d_xbar[b * CDIM + c];
}

// ---------------- launch ----------------
extern "C" void kernel_launch(void* const* d_in, const int* in_sizes, int n_in,
                              void* d_out, int out_size) {
    const float* x     = (const float*)d_in[0];
    const float* Wq    = (const float*)d_in[1];
    const float* Wk    = (const float*)d_in[2];
    const float* Wv    = (const float*)d_in[3];
    const float* gamma = (const float*)d_in[4];
    float* out    = (float*)d_out;
    float* pooled = out;                 // [B,C,1,1] = 2048 floats
    float* beta   = out + BATCH * CDIM;  // [B,N,N]

    cudaFuncSetAttribute(fg_kernel, cudaFuncAttributeMaxDynamicSharedMemorySize, FG_SMEM);
    cudaFuncSetAttribute(attn_fused_kernel, cudaFuncAttributeMaxDynamicSharedMemorySize,
                         ATTN_SMEM);

    zero_kernel<<<64, 256>>>();
    wsplit_kernel<<<(128 * CDIM + 255) / 256, 256>>>(Wq, Wk);
    fg_kernel<<<dim3(32, BATCH), 256, FG_SMEM>>>(x);
    attn_fused_kernel<<<dim3(32, BATCH), 256, ATTN_SMEM>>>(beta);
    pool1_kernel<<<dim3(CDIM / 8, BATCH), 256>>>(x);
    pool2_kernel<<<dim3(CDIM / 8, BATCH), 256>>>(Wv, gamma, pooled);
}

// round 5
// speedup vs baseline: 1.0296x; 1.0296x over previous
#include <cuda_runtime.h>
#include <cuda_bf16.h>
#include <cstdint>
#include <cstddef>

#define BATCH 4
#define CDIM  512
#define KDIM  64
#define NDIM  4096
#define NN    ((size_t)NDIM * NDIM)

// ---------------- device scratch (no allocs allowed) ----------------
// f/g operand arrays are stored PRE-SWIZZLED (XOR-16B within each
// 128-row x 64-col tile; pattern depends only on row&7) so attention can
// bulk-copy them linearly.
__device__ __align__(128) __nv_bfloat16 d_fa_hi[BATCH * NDIM * KDIM]; // f, i-major
__device__ __align__(128) __nv_bfloat16 d_fa_lo[BATCH * NDIM * KDIM];
__device__ __align__(128) __nv_bfloat16 d_gb_hi[BATCH * NDIM * KDIM]; // g, j-major
__device__ __align__(128) __nv_bfloat16 d_gb_lo[BATCH * NDIM * KDIM];
__device__ __align__(16) __nv_bfloat16 d_w_hi[128 * CDIM];            // [Wq;Wk] split
__device__ __align__(16) __nv_bfloat16 d_w_lo[128 * CDIM];
__device__ float d_rowsum[BATCH * NDIM];  // row sums of beta
__device__ float d_y[BATCH * CDIM];
__device__ float d_xbar[BATCH * CDIM];

__device__ __forceinline__ float fast_exp(float x) {
    float y;
    asm("ex2.approx.ftz.f32 %0, %1;" : "=f"(y) : "f"(x * 1.4426950408889634f));
    return y;
}

__device__ __forceinline__ float warp_sum(float v) {
    #pragma unroll
    for (int o = 16; o; o >>= 1) v += __shfl_xor_sync(0xFFFFFFFFu, v, o);
    return v;
}

__device__ __forceinline__ uint32_t smem_u32(const void* p) {
    uint32_t a;
    asm("{ .reg .u64 t; cvta.to.shared.u64 t, %1; cvt.u32.u64 %0, t; }"
        : "=r"(a) : "l"(p));
    return a;
}

// A fragment (m16 x k16) via ldmatrix x4 from m-major SW-swizzled [rows][64] bf16 tile
__device__ __forceinline__ void ldA(uint32_t tile, int rbase, int kc, int lane, uint32_t* a) {
    int r = rbase + (lane & 15);
    int c = kc + (lane >> 4);
    uint32_t addr = tile + r * 128 + ((c ^ (r & 7)) << 4);
    asm volatile("ldmatrix.sync.aligned.m8n8.x4.shared.b16 {%0,%1,%2,%3}, [%4];"
                 : "=r"(a[0]), "=r"(a[1]), "=r"(a[2]), "=r"(a[3]) : "r"(addr));
}

// B fragment (n8 x k16) via ldmatrix x2
__device__ __forceinline__ void ldB(uint32_t tile, int rbase, int kc, int lane, uint32_t* bb) {
    int r = rbase + (lane & 7);
    int c = kc + ((lane >> 3) & 1);
    uint32_t addr = tile + r * 128 + ((c ^ (r & 7)) << 4);
    asm volatile("ldmatrix.sync.aligned.m8n8.x2.shared.b16 {%0,%1}, [%2];"
                 : "=r"(bb[0]), "=r"(bb[1]) : "r"(addr));
}

__device__ __forceinline__ void mma_bf16(float* acc, const uint32_t* a, const uint32_t* bb) {
    asm volatile(
        "mma.sync.aligned.m16n8k16.row.col.f32.bf16.bf16.f32 "
        "{%0,%1,%2,%3}, {%4,%5,%6,%7}, {%8,%9}, {%0,%1,%2,%3};"
        : "+f"(acc[0]), "+f"(acc[1]), "+f"(acc[2]), "+f"(acc[3])
        : "r"(a[0]), "r"(a[1]), "r"(a[2]), "r"(a[3]), "r"(bb[0]), "r"(bb[1]));
}

// ---------------- mbarrier + bulk-copy helpers (sm_90 baseline PTX) ----------------
#define MBARRIER_INIT(mbar, count) \
    asm volatile("mbarrier.init.shared.b64 [%0], %1;" \
                 :: "r"((uint32_t)(mbar)), "r"((uint32_t)(count)) : "memory")
#define MBARRIER_EXPECT_TX(mbar, bytes) \
    asm volatile("mbarrier.arrive.expect_tx.shared.b64 _, [%0], %1;" \
                 :: "r"((uint32_t)(mbar)), "r"((uint32_t)(bytes)) : "memory")
#define FENCE_PROXY_ASYNC() \
    asm volatile("fence.proxy.async.shared::cta;" ::: "memory")
#define CP_BULK(dst_smem, src_gmem, bytes, mbar) \
    asm volatile("cp.async.bulk.shared::cta.global.mbarrier::complete_tx::bytes " \
                 "[%0], [%1], %2, [%3];" \
                 :: "r"((uint32_t)(dst_smem)), "l"(src_gmem), "r"((uint32_t)(bytes)), \
                    "r"((uint32_t)(mbar)) : "memory")

__device__ __forceinline__ void mbar_wait_parity(uint32_t mbar, uint32_t parity) {
    uint32_t done;
    asm volatile(
        "{\n\t.reg .pred p;\n\t"
        "mbarrier.try_wait.parity.acquire.cta.shared::cta.b64 p, [%1], %2;\n\t"
        "selp.b32 %0, 1, 0, p;\n\t}"
        : "=r"(done) : "r"(mbar), "r"(parity) : "memory");
    if (!done) {
        asm volatile(
            "{\n\t.reg .pred P1;\n\t"
            "WAIT_LOOP_%=:\n\t"
            "mbarrier.try_wait.parity.acquire.cta.shared::cta.b64 P1, [%0], %1, 0x989680;\n\t"
            "@P1 bra.uni WAIT_DONE_%=;\n\t"
            "bra.uni WAIT_LOOP_%=;\n\t"
            "WAIT_DONE_%=:\n\t}"
            :: "r"(mbar), "r"(parity) : "memory");
    }
}

// ---------------- zero rowsum accumulator ----------------
__global__ void zero_kernel() {
    int i = blockIdx.x * blockDim.x + threadIdx.x;
    if (i < BATCH * NDIM) d_rowsum[i] = 0.f;
}

// ---------------- W split prep: [Wq;Wk] fp32 -> bf16 hi/lo ----------------
__global__ __launch_bounds__(256) void wsplit_kernel(const float* __restrict__ Wq,
                                                     const float* __restrict__ Wk) {
    int idx = blockIdx.x * blockDim.x + threadIdx.x;
    if (idx >= 128 * CDIM) return;
    int m = idx >> 9;
    int c = idx & 511;
    float w = (m < 64) ? Wq[m * CDIM + c] : Wk[(m - 64) * CDIM + c];
    __nv_bfloat16 hi = __float2bfloat16(w);
    d_w_hi[idx] = hi;
    d_w_lo[idx] = __float2bfloat16(w - __bfloat162float(hi));
}

// ---------------- FG: [f;g] = [Wq;Wk] @ x[b] via bf16x3 mma.sync ----------------
#define FG_SMEM (128 * 132 * 4)  // 67584

__global__ __launch_bounds__(256) void fg_kernel(const float* __restrict__ x) {
    extern __shared__ __align__(1024) char dynsm[];
    uint32_t smem_base = smem_u32(dynsm);
    uint4* sWhi = (uint4*)(dynsm);
    uint4* sWlo = (uint4*)(dynsm + 16384);
    uint4* sXhi = (uint4*)(dynsm + 32768);
    uint4* sXlo = (uint4*)(dynsm + 49152);
    float* S = (float*)dynsm;  // [128][132] alias after mainloop

    int b = blockIdx.y;
    int i0 = blockIdx.x * 128;
    int tid = threadIdx.x;
    int lane = tid & 31, wid = tid >> 5;
    int wm = wid >> 2, wn = wid & 3;
    const float* xb = x + (size_t)b * CDIM * NDIM;

    float acc[4][4][4];
    #pragma unroll
    for (int mf = 0; mf < 4; mf++)
        #pragma unroll
        for (int nf = 0; nf < 4; nf++)
            #pragma unroll
            for (int e = 0; e < 4; e++) acc[mf][nf][e] = 0.f;

    for (int c0 = 0; c0 < CDIM; c0 += 64) {
        #pragma unroll
        for (int t = 0; t < 4; t++) {
            int idx = tid + t * 256;
            int m = idx >> 3, ch = idx & 7;
            int soff = m * 8 + (ch ^ (m & 7));
            sWhi[soff] = ((const uint4*)(d_w_hi + (size_t)m * CDIM + c0))[ch];
            sWlo[soff] = ((const uint4*)(d_w_lo + (size_t)m * CDIM + c0))[ch];
        }
        #pragma unroll
        for (int t = 0; t < 4; t++) {
            int idx = tid + t * 256;
            int n = idx & 127, oct = idx >> 7;
            const float* src = xb + (size_t)(c0 + oct * 8) * NDIM + i0 + n;
            __align__(16) __nv_bfloat16 h8[8], l8[8];
            #pragma unroll
            for (int j = 0; j < 8; j++) {
                float v = src[(size_t)j * NDIM];
                __nv_bfloat16 hi = __float2bfloat16(v);
                h8[j] = hi;
                l8[j] = __float2bfloat16(v - __bfloat162float(hi));
            }
            int soff = n * 8 + (oct ^ (n & 7));
            sXhi[soff] = *(uint4*)h8;
            sXlo[soff] = *(uint4*)l8;
        }
        __syncthreads();

        uint32_t tA = smem_base, tAlo = smem_base + 16384;
        uint32_t tB = smem_base + 32768, tBlo = smem_base + 49152;
        #pragma unroll
        for (int ks = 0; ks < 4; ks++) {
            int kc = ks * 2;
            uint32_t ahi[4][4], alo[4][4], bhi[4][2], blo[4][2];
            #pragma unroll
            for (int mf = 0; mf < 4; mf++) ldA(tA, wm * 64 + mf * 16, kc, lane, ahi[mf]);
            #pragma unroll
            for (int nf = 0; nf < 4; nf++) ldB(tB, wn * 32 + nf * 8, kc, lane, bhi[nf]);
            #pragma unroll
            for (int mf = 0; mf < 4; mf++)
                #pragma unroll
                for (int nf = 0; nf < 4; nf++) mma_bf16(acc[mf][nf], ahi[mf], bhi[nf]);
            #pragma unroll
            for (int mf = 0; mf < 4; mf++) ldA(tAlo, wm * 64 + mf * 16, kc, lane, alo[mf]);
            #pragma unroll
            for (int mf = 0; mf < 4; mf++)
                #pragma unroll
                for (int nf = 0; nf < 4; nf++) mma_bf16(acc[mf][nf], alo[mf], bhi[nf]);
            #pragma unroll
            for (int nf = 0; nf < 4; nf++) ldB(tBlo, wn * 32 + nf * 8, kc, lane, blo[nf]);
            #pragma unroll
            for (int mf = 0; mf < 4; mf++)
                #pragma unroll
                for (int nf = 0; nf < 4; nf++) mma_bf16(acc[mf][nf], ahi[mf], blo[nf]);
        }
        __syncthreads();
    }

    #pragma unroll
    for (int mf = 0; mf < 4; mf++)
        #pragma unroll
        for (int nf = 0; nf < 4; nf++) {
            int r = wm * 64 + mf * 16 + (lane >> 2);
            int cc = wn * 32 + nf * 8 + (lane & 3) * 2;
            S[r * 132 + cc]           = acc[mf][nf][0];
            S[r * 132 + cc + 1]       = acc[mf][nf][1];
            S[(r + 8) * 132 + cc]     = acc[mf][nf][2];
            S[(r + 8) * 132 + cc + 1] = acc[mf][nf][3];
        }
    __syncthreads();

    // write split bf16 PRE-SWIZZLED: chunk index XORed with (row & 7)
    int arr = lane >> 3, chunk = lane & 7;
    int mbase = (arr >= 2 ? 64 : 0) + chunk * 8;
    __nv_bfloat16* dst = (arr == 0) ? d_fa_hi : (arr == 1) ? d_fa_lo
                       : (arr == 2) ? d_gb_hi : d_gb_lo;
    for (int r = wid; r < 128; r += 8) {
        __align__(16) __nv_bfloat16 vals[8];
        #pragma unroll
        for (int e = 0; e < 8; e++) {
            float v = S[(mbase + e) * 132 + r];
            __nv_bfloat16 hi = __float2bfloat16(v);
            if (arr & 1) vals[e] = __float2bfloat16(v - __bfloat162float(hi));
            else         vals[e] = hi;
        }
        int chs = chunk ^ (r & 7);
        *(uint4*)(dst + ((size_t)b * NDIM + i0 + r) * KDIM + chs * 8) = *(uint4*)vals;
    }
}

// ---------------- fused attention: one CTA per (b, 64-j strip), 2 CTAs/SM -------
// Tile 128(i) x 64(j).  Phase 1 (i-tiles 0..31): Z[j] in registers.
// Phase 2: recompute, beta = exp(s)/Z, rowsum.  B resident; A 2-stage bulk ring.
// SMEM: [0,16K) B hi/lo; [16K,80K) A ring; sZ @81920; zbuf @82176; mbars @83200.
#define ATTN_SMEM 83456

__global__ __launch_bounds__(256, 2) void attn_fused_kernel(float* __restrict__ beta_out) {
    extern __shared__ __align__(1024) char dynsm[];
    uint32_t smem_base = smem_u32(dynsm);
    const uint32_t SB  = smem_base;             // B hi @0, lo @8192
    const uint32_t SA0 = smem_base + 16384;     // ring stage s at +s*32768
    float* sZ   = (float*)(dynsm + 81920);      // 64 floats
    float* zbuf = (float*)(dynsm + 82176);      // 4 x 64 floats
    const uint32_t MB_FULL0 = smem_base + 83200;
    const uint32_t MB_FULL1 = smem_base + 83208;
    const uint32_t MB_B     = smem_base + 83216;

    int b  = blockIdx.y;
    int j0 = blockIdx.x * 64;
    int tid = threadIdx.x;
    int lane = tid & 31, wid = tid >> 5;
    int wn = wid & 1, wm = wid >> 1;   // 4 m-groups of 32 rows, 2 n-groups of 32 cols

    const char* gBhi = (const char*)(d_gb_hi + ((size_t)b * NDIM + j0) * KDIM);
    const char* gBlo = (const char*)(d_gb_lo + ((size_t)b * NDIM + j0) * KDIM);
    const char* gAhi = (const char*)(d_fa_hi + (size_t)b * NDIM * KDIM);
    const char* gAlo = (const char*)(d_fa_lo + (size_t)b * NDIM * KDIM);

    if (tid == 0) {
        MBARRIER_INIT(MB_FULL0, 1);
        MBARRIER_INIT(MB_FULL1, 1);
        MBARRIER_INIT(MB_B, 1);
        FENCE_PROXY_ASYNC();
        MBARRIER_EXPECT_TX(MB_B, 16384);
        CP_BULK(SB,        gBhi, 8192, MB_B);
        CP_BULK(SB + 8192, gBlo, 8192, MB_B);
        MBARRIER_EXPECT_TX(MB_FULL0, 32768);
        CP_BULK(SA0,         gAhi, 16384, MB_FULL0);
        CP_BULK(SA0 + 16384, gAlo, 16384, MB_FULL0);
        MBARRIER_EXPECT_TX(MB_FULL1, 32768);
        CP_BULK(SA0 + 32768, gAhi + 16384, 16384, MB_FULL1);
        CP_BULK(SA0 + 49152, gAlo + 16384, 16384, MB_FULL1);
    }
    __syncthreads();
    mbar_wait_parity(MB_B, 0);

    uint32_t tB = SB, tBlo = SB + 8192;
    float zp0[4] = {0.f, 0.f, 0.f, 0.f};
    float zp1[4] = {0.f, 0.f, 0.f, 0.f};
    float* ob = beta_out + (size_t)b * NN;

    for (int n = 0; n < 64; n++) {
        int s = n & 1;
        uint32_t mb = s ? MB_FULL1 : MB_FULL0;
        mbar_wait_parity(mb, (n >> 1) & 1);

        uint32_t tA = SA0 + s * 32768, tAlo = tA + 16384;
        float acc[2][4][4];
        #pragma unroll
        for (int mf = 0; mf < 2; mf++)
            #pragma unroll
            for (int nf = 0; nf < 4; nf++)
                #pragma unroll
                for (int e = 0; e < 4; e++) acc[mf][nf][e] = 0.f;

        #pragma unroll
        for (int ks = 0; ks < 4; ks++) {
            int kc = ks * 2;
            uint32_t ahi[2][4], alo[2][4], bhi[4][2], blo[4][2];
            #pragma unroll
            for (int mf = 0; mf < 2; mf++) ldA(tA, wm * 32 + mf * 16, kc, lane, ahi[mf]);
            #pragma unroll
            for (int nf = 0; nf < 4; nf++) ldB(tB, wn * 32 + nf * 8, kc, lane, bhi[nf]);
            #pragma unroll
            for (int mf = 0; mf < 2; mf++)
                #pragma unroll
                for (int nf = 0; nf < 4; nf++) mma_bf16(acc[mf][nf], ahi[mf], bhi[nf]);
            #pragma unroll
            for (int mf = 0; mf < 2; mf++) ldA(tAlo, wm * 32 + mf * 16, kc, lane, alo[mf]);
            #pragma unroll
            for (int mf = 0; mf < 2; mf++)
                #pragma unroll
                for (int nf = 0; nf < 4; nf++) mma_bf16(acc[mf][nf], alo[mf], bhi[nf]);
            #pragma unroll
            for (int nf = 0; nf < 4; nf++) ldB(tBlo, wn * 32 + nf * 8, kc, lane, blo[nf]);
            #pragma unroll
            for (int mf = 0; mf < 2; mf++)
                #pragma unroll
                for (int nf = 0; nf < 4; nf++) mma_bf16(acc[mf][nf], ahi[mf], blo[nf]);
        }
        __syncthreads();  // all warps done reading ring stage s

        if (tid == 0 && n < 62) {
            size_t t = (size_t)((n + 2) & 31) * 16384;
            MBARRIER_EXPECT_TX(mb, 32768);
            CP_BULK(tA,   gAhi + t, 16384, mb);
            CP_BULK(tAlo, gAlo + t, 16384, mb);
        }

        if (n < 32) {
            // phase 1: lane-local Z partials
            #pragma unroll
            for (int nf = 0; nf < 4; nf++) {
                float s0 = 0.f, s1 = 0.f;
                #pragma unroll
                for (int mf = 0; mf < 2; mf++) {
                    s0 += fast_exp(acc[mf][nf][0]) + fast_exp(acc[mf][nf][2]);
                    s1 += fast_exp(acc[mf][nf][1]) + fast_exp(acc[mf][nf][3]);
                }
                zp0[nf] += s0;
                zp1[nf] += s1;
            }
            if (n == 31) {
                // finalize Z: butterfly over the 8 row-groups, merge 4 wm groups
                #pragma unroll
                for (int nf = 0; nf < 4; nf++) {
                    #pragma unroll
                    for (int o = 4; o < 32; o <<= 1) {
                        zp0[nf] += __shfl_xor_sync(0xFFFFFFFFu, zp0[nf], o);
                        zp1[nf] += __shfl_xor_sync(0xFFFFFFFFu, zp1[nf], o);
                    }
                }
                if (lane < 4) {
                    #pragma unroll
                    for (int nf = 0; nf < 4; nf++) {
                        int cc = wn * 32 + nf * 8 + lane * 2;
                        zbuf[wm * 64 + cc]     = zp0[nf];
                        zbuf[wm * 64 + cc + 1] = zp1[nf];
                    }
                }
                __syncthreads();
                if (tid < 64)
                    sZ[tid] = 1.0f / (zbuf[tid] + zbuf[64 + tid] +
                                      zbuf[128 + tid] + zbuf[192 + tid]);
                __syncthreads();
            }
        } else {
            // phase 2: beta = exp(s)/Z, accumulate rowsum
            int i0 = (n - 32) * 128;
            float rs0[2], rs1[2];
            #pragma unroll
            for (int mf = 0; mf < 2; mf++) { rs0[mf] = 0.f; rs1[mf] = 0.f; }
            #pragma unroll
            for (int mf = 0; mf < 2; mf++) {
                int r = wm * 32 + mf * 16 + (lane >> 2);
                #pragma unroll
                for (int nf = 0; nf < 4; nf++) {
                    int cc = wn * 32 + nf * 8 + (lane & 3) * 2;
                    float iz0 = sZ[cc], iz1 = sZ[cc + 1];
                    float v0 = fast_exp(acc[mf][nf][0]) * iz0;
                    float v1 = fast_exp(acc[mf][nf][1]) * iz1;
                    float v2 = fast_exp(acc[mf][nf][2]) * iz0;
                    float v3 = fast_exp(acc[mf][nf][3]) * iz1;
                    *(float2*)(ob + (size_t)(i0 + r) * NDIM + j0 + cc)     = make_float2(v0, v1);
                    *(float2*)(ob + (size_t)(i0 + r + 8) * NDIM + j0 + cc) = make_float2(v2, v3);
                    rs0[mf] += v0 + v1;
                    rs1[mf] += v2 + v3;
                }
            }
            #pragma unroll
            for (int mf = 0; mf < 2; mf++) {
                #pragma unroll
                for (int o = 1; o < 4; o <<= 1) {
                    rs0[mf] += __shfl_xor_sync(0xFFFFFFFFu, rs0[mf], o);
                    rs1[mf] += __shfl_xor_sync(0xFFFFFFFFu, rs1[mf], o);
                }
            }
            if ((lane & 3) == 0) {
                #pragma unroll
                for (int mf = 0; mf < 2; mf++) {
                    int r = wm * 32 + mf * 16 + (lane >> 2);
                    atomicAdd(&d_rowsum[b * NDIM + i0 + r], rs0[mf]);
                    atomicAdd(&d_rowsum[b * NDIM + i0 + r + 8], rs1[mf]);
                }
            }
        }
    }
}

// ---------------- pooled epilogue ----------------
__global__ __launch_bounds__(256) void pool1_kernel(const float* __restrict__ x) {
    int b = blockIdx.y;
    int cc = blockIdx.x * 8 + (threadIdx.x >> 5);
    int lane = threadIdx.x & 31;
    const float* xr = x + ((size_t)b * CDIM + cc) * NDIM;
    const float* rs = d_rowsum + b * NDIM;
    float ay = 0.f, ax = 0.f;
    for (int i = lane; i < NDIM; i += 32) {
        float xv = xr[i];
        ay += xv * rs[i];
        ax += xv;
    }
    ay = warp_sum(ay); ax = warp_sum(ax);
    if (lane == 0) {
        d_y[b * CDIM + cc]    = ay * (1.0f / NDIM);
        d_xbar[b * CDIM + cc] = ax * (1.0f / NDIM);
    }
}

__global__ __launch_bounds__(256) void pool2_kernel(const float* __restrict__ Wv,
                                                    const float* __restrict__ gamma,
                                                    float* __restrict__ out) {
    int b = blockIdx.y;
    int c = blockIdx.x * 8 + (threadIdx.x >> 5);
    int lane = threadIdx.x & 31;
    const float* wr = Wv + (size_t)c * CDIM;
    const float* yb = d_y + b * CDIM;
    float a = 0.f;
    for (int k = lane; k < CDIM; k += 32) a += wr[k] * yb[k];
    a = warp_sum(a);
    if (lane == 0) out[b * CDIM + c] = gamma[0] * a + d_xbar[b * CDIM + c];
}

// ---------------- launch ----------------
extern "C" void kernel_launch(void* const* d_in, const int* in_sizes, int n_in,
                              void* d_out, int out_size) {
    const float* x     = (const float*)d_in[0];
    const float* Wq    = (const float*)d_in[1];
    const float* Wk    = (const float*)d_in[2];
    const float* Wv    = (const float*)d_in[3];
    const float* gamma = (const float*)d_in[4];
    float* out    = (float*)d_out;
    float* pooled = out;                 // [B,C,1,1] = 2048 floats
    float* beta   = out + BATCH * CDIM;  // [B,N,N]

    cudaFuncSetAttribute(fg_kernel, cudaFuncAttributeMaxDynamicSharedMemorySize, FG_SMEM);
    cudaFuncSetAttribute(attn_fused_kernel, cudaFuncAttributeMaxDynamicSharedMemorySize,
                         ATTN_SMEM);

    zero_kernel<<<64, 256>>>();
    wsplit_kernel<<<(128 * CDIM + 255) / 256, 256>>>(Wq, Wk);
    fg_kernel<<<dim3(32, BATCH), 256, FG_SMEM>>>(x);
    attn_fused_kernel<<<dim3(64, BATCH), 256, ATTN_SMEM>>>(beta);
    pool1_kernel<<<dim3(CDIM / 8, BATCH), 256>>>(x);
    pool2_kernel<<<dim3(CDIM / 8, BATCH), 256>>>(Wv, gamma, pooled);
}

// round 6
// speedup vs baseline: 1.1312x; 1.0986x over previous
#include <cuda_runtime.h>
#include <cuda_bf16.h>
#include <cstdint>
#include <cstddef>

#define BATCH 4
#define CDIM  512
#define KDIM  64
#define NDIM  4096
#define NN    ((size_t)NDIM * NDIM)

// ---------------- device scratch (no allocs allowed) ----------------
// f/g operand arrays are stored PRE-SWIZZLED (XOR-16B within each
// 128-row x 64-col tile; pattern depends only on row&7) so attention can
// bulk-copy them linearly.
__device__ __align__(128) __nv_bfloat16 d_fa_hi[BATCH * NDIM * KDIM]; // f, i-major
__device__ __align__(128) __nv_bfloat16 d_fa_lo[BATCH * NDIM * KDIM];
__device__ __align__(128) __nv_bfloat16 d_gb_hi[BATCH * NDIM * KDIM]; // g, j-major
__device__ __align__(128) __nv_bfloat16 d_gb_lo[BATCH * NDIM * KDIM];
__device__ __align__(16) __nv_bfloat16 d_w_hi[128 * CDIM];            // [Wq;Wk] split
__device__ __align__(16) __nv_bfloat16 d_w_lo[128 * CDIM];
__device__ float d_rowsum[BATCH * NDIM];  // row sums of beta
__device__ float d_y[BATCH * CDIM];
__device__ float d_xbar[BATCH * CDIM];

__device__ __forceinline__ float fast_exp(float x) {
    float y;
    asm("ex2.approx.ftz.f32 %0, %1;" : "=f"(y) : "f"(x * 1.4426950408889634f));
    return y;
}

__device__ __forceinline__ float warp_sum(float v) {
    #pragma unroll
    for (int o = 16; o; o >>= 1) v += __shfl_xor_sync(0xFFFFFFFFu, v, o);
    return v;
}

__device__ __forceinline__ uint32_t smem_u32(const void* p) {
    uint32_t a;
    asm("{ .reg .u64 t; cvta.to.shared.u64 t, %1; cvt.u32.u64 %0, t; }"
        : "=r"(a) : "l"(p));
    return a;
}

// A fragment (m16 x k16) via ldmatrix x4 from m-major SW-swizzled [rows][64] bf16 tile
__device__ __forceinline__ void ldA(uint32_t tile, int rbase, int kc, int lane, uint32_t* a) {
    int r = rbase + (lane & 15);
    int c = kc + (lane >> 4);
    uint32_t addr = tile + r * 128 + ((c ^ (r & 7)) << 4);
    asm volatile("ldmatrix.sync.aligned.m8n8.x4.shared.b16 {%0,%1,%2,%3}, [%4];"
                 : "=r"(a[0]), "=r"(a[1]), "=r"(a[2]), "=r"(a[3]) : "r"(addr));
}

// B fragment (n8 x k16) via ldmatrix x2
__device__ __forceinline__ void ldB(uint32_t tile, int rbase, int kc, int lane, uint32_t* bb) {
    int r = rbase + (lane & 7);
    int c = kc + ((lane >> 3) & 1);
    uint32_t addr = tile + r * 128 + ((c ^ (r & 7)) << 4);
    asm volatile("ldmatrix.sync.aligned.m8n8.x2.shared.b16 {%0,%1}, [%2];"
                 : "=r"(bb[0]), "=r"(bb[1]) : "r"(addr));
}

__device__ __forceinline__ void mma_bf16(float* acc, const uint32_t* a, const uint32_t* bb) {
    asm volatile(
        "mma.sync.aligned.m16n8k16.row.col.f32.bf16.bf16.f32 "
        "{%0,%1,%2,%3}, {%4,%5,%6,%7}, {%8,%9}, {%0,%1,%2,%3};"
        : "+f"(acc[0]), "+f"(acc[1]), "+f"(acc[2]), "+f"(acc[3])
        : "r"(a[0]), "r"(a[1]), "r"(a[2]), "r"(a[3]), "r"(bb[0]), "r"(bb[1]));
}

// ---------------- mbarrier + bulk-copy helpers (sm_90 baseline PTX) ----------------
#define MBARRIER_INIT(mbar, count) \
    asm volatile("mbarrier.init.shared.b64 [%0], %1;" \
                 :: "r"((uint32_t)(mbar)), "r"((uint32_t)(count)) : "memory")
#define MBARRIER_EXPECT_TX(mbar, bytes) \
    asm volatile("mbarrier.arrive.expect_tx.shared.b64 _, [%0], %1;" \
                 :: "r"((uint32_t)(mbar)), "r"((uint32_t)(bytes)) : "memory")
#define MBARRIER_ARRIVE(mbar) \
    asm volatile("mbarrier.arrive.shared.b64 _, [%0];" \
                 :: "r"((uint32_t)(mbar)) : "memory")
#define FENCE_PROXY_ASYNC() \
    asm volatile("fence.proxy.async.shared::cta;" ::: "memory")
#define CP_BULK(dst_smem, src_gmem, bytes, mbar) \
    asm volatile("cp.async.bulk.shared::cta.global.mbarrier::complete_tx::bytes " \
                 "[%0], [%1], %2, [%3];" \
                 :: "r"((uint32_t)(dst_smem)), "l"(src_gmem), "r"((uint32_t)(bytes)), \
                    "r"((uint32_t)(mbar)) : "memory")

__device__ __forceinline__ void mbar_wait_parity(uint32_t mbar, uint32_t parity) {
    uint32_t done;
    asm volatile(
        "{\n\t.reg .pred p;\n\t"
        "mbarrier.try_wait.parity.acquire.cta.shared::cta.b64 p, [%1], %2;\n\t"
        "selp.b32 %0, 1, 0, p;\n\t}"
        : "=r"(done) : "r"(mbar), "r"(parity) : "memory");
    if (!done) {
        asm volatile(
            "{\n\t.reg .pred P1;\n\t"
            "WAIT_LOOP_%=:\n\t"
            "mbarrier.try_wait.parity.acquire.cta.shared::cta.b64 P1, [%0], %1, 0x989680;\n\t"
            "@P1 bra.uni WAIT_DONE_%=;\n\t"
            "bra.uni WAIT_LOOP_%=;\n\t"
            "WAIT_DONE_%=:\n\t}"
            :: "r"(mbar), "r"(parity) : "memory");
    }
}

// ---------------- W split prep + rowsum zero ----------------
__global__ __launch_bounds__(256) void wsplit_kernel(const float* __restrict__ Wq,
                                                     const float* __restrict__ Wk) {
    int idx = blockIdx.x * blockDim.x + threadIdx.x;
    if (idx < BATCH * NDIM) d_rowsum[idx] = 0.f;
    if (idx >= 128 * CDIM) return;
    int m = idx >> 9;
    int c = idx & 511;
    float w = (m < 64) ? Wq[m * CDIM + c] : Wk[(m - 64) * CDIM + c];
    __nv_bfloat16 hi = __float2bfloat16(w);
    d_w_hi[idx] = hi;
    d_w_lo[idx] = __float2bfloat16(w - __bfloat162float(hi));
}

// ---------------- FG: [f;g] = [Wq;Wk] @ x[b] via bf16x3 mma.sync ----------------
#define FG_SMEM (128 * 132 * 4)  // 67584

__global__ __launch_bounds__(256) void fg_kernel(const float* __restrict__ x) {
    extern __shared__ __align__(1024) char dynsm[];
    uint32_t smem_base = smem_u32(dynsm);
    uint4* sWhi = (uint4*)(dynsm);
    uint4* sWlo = (uint4*)(dynsm + 16384);
    uint4* sXhi = (uint4*)(dynsm + 32768);
    uint4* sXlo = (uint4*)(dynsm + 49152);
    float* S = (float*)dynsm;  // [128][132] alias after mainloop

    int b = blockIdx.y;
    int i0 = blockIdx.x * 128;
    int tid = threadIdx.x;
    int lane = tid & 31, wid = tid >> 5;
    int wm = wid >> 2, wn = wid & 3;
    const float* xb = x + (size_t)b * CDIM * NDIM;

    float acc[4][4][4];
    #pragma unroll
    for (int mf = 0; mf < 4; mf++)
        #pragma unroll
        for (int nf = 0; nf < 4; nf++)
            #pragma unroll
            for (int e = 0; e < 4; e++) acc[mf][nf][e] = 0.f;

    for (int c0 = 0; c0 < CDIM; c0 += 64) {
        #pragma unroll
        for (int t = 0; t < 4; t++) {
            int idx = tid + t * 256;
            int m = idx >> 3, ch = idx & 7;
            int soff = m * 8 + (ch ^ (m & 7));
            sWhi[soff] = ((const uint4*)(d_w_hi + (size_t)m * CDIM + c0))[ch];
            sWlo[soff] = ((const uint4*)(d_w_lo + (size_t)m * CDIM + c0))[ch];
        }
        #pragma unroll
        for (int t = 0; t < 4; t++) {
            int idx = tid + t * 256;
            int n = idx & 127, oct = idx >> 7;
            const float* src = xb + (size_t)(c0 + oct * 8) * NDIM + i0 + n;
            __align__(16) __nv_bfloat16 h8[8], l8[8];
            #pragma unroll
            for (int j = 0; j < 8; j++) {
                float v = src[(size_t)j * NDIM];
                __nv_bfloat16 hi = __float2bfloat16(v);
                h8[j] = hi;
                l8[j] = __float2bfloat16(v - __bfloat162float(hi));
            }
            int soff = n * 8 + (oct ^ (n & 7));
            sXhi[soff] = *(uint4*)h8;
            sXlo[soff] = *(uint4*)l8;
        }
        __syncthreads();

        uint32_t tA = smem_base, tAlo = smem_base + 16384;
        uint32_t tB = smem_base + 32768, tBlo = smem_base + 49152;
        #pragma unroll
        for (int ks = 0; ks < 4; ks++) {
            int kc = ks * 2;
            uint32_t ahi[4][4], alo[4][4], bhi[4][2], blo[4][2];
            #pragma unroll
            for (int mf = 0; mf < 4; mf++) ldA(tA, wm * 64 + mf * 16, kc, lane, ahi[mf]);
            #pragma unroll
            for (int nf = 0; nf < 4; nf++) ldB(tB, wn * 32 + nf * 8, kc, lane, bhi[nf]);
            #pragma unroll
            for (int mf = 0; mf < 4; mf++)
                #pragma unroll
                for (int nf = 0; nf < 4; nf++) mma_bf16(acc[mf][nf], ahi[mf], bhi[nf]);
            #pragma unroll
            for (int mf = 0; mf < 4; mf++) ldA(tAlo, wm * 64 + mf * 16, kc, lane, alo[mf]);
            #pragma unroll
            for (int mf = 0; mf < 4; mf++)
                #pragma unroll
                for (int nf = 0; nf < 4; nf++) mma_bf16(acc[mf][nf], alo[mf], bhi[nf]);
            #pragma unroll
            for (int nf = 0; nf < 4; nf++) ldB(tBlo, wn * 32 + nf * 8, kc, lane, blo[nf]);
            #pragma unroll
            for (int mf = 0; mf < 4; mf++)
                #pragma unroll
                for (int nf = 0; nf < 4; nf++) mma_bf16(acc[mf][nf], ahi[mf], blo[nf]);
        }
        __syncthreads();
    }

    #pragma unroll
    for (int mf = 0; mf < 4; mf++)
        #pragma unroll
        for (int nf = 0; nf < 4; nf++) {
            int r = wm * 64 + mf * 16 + (lane >> 2);
            int cc = wn * 32 + nf * 8 + (lane & 3) * 2;
            S[r * 132 + cc]           = acc[mf][nf][0];
            S[r * 132 + cc + 1]       = acc[mf][nf][1];
            S[(r + 8) * 132 + cc]     = acc[mf][nf][2];
            S[(r + 8) * 132 + cc + 1] = acc[mf][nf][3];
        }
    __syncthreads();

    // write split bf16 PRE-SWIZZLED: chunk index XORed with (row & 7)
    int arr = lane >> 3, chunk = lane & 7;
    int mbase = (arr >= 2 ? 64 : 0) + chunk * 8;
    __nv_bfloat16* dst = (arr == 0) ? d_fa_hi : (arr == 1) ? d_fa_lo
                       : (arr == 2) ? d_gb_hi : d_gb_lo;
    for (int r = wid; r < 128; r += 8) {
        __align__(16) __nv_bfloat16 vals[8];
        #pragma unroll
        for (int e = 0; e < 8; e++) {
            float v = S[(mbase + e) * 132 + r];
            __nv_bfloat16 hi = __float2bfloat16(v);
            if (arr & 1) vals[e] = __float2bfloat16(v - __bfloat162float(hi));
            else         vals[e] = hi;
        }
        int chs = chunk ^ (r & 7);
        *(uint4*)(dst + ((size_t)b * NDIM + i0 + r) * KDIM + chs * 8) = *(uint4*)vals;
    }
}

// ---------------- fused attention: one CTA per (b, 64-j strip), 2 CTAs/SM -------
// Tile 128(i) x 64(j).  Phase 1 (i-tiles 0..31): Z[j] in registers.
// Phase 2: recompute, beta = exp(s)/Z, rowsum.  B resident; A 2-stage bulk ring.
// Warp-desynchronized ring: consumers arrive on empty[s] (count=8) after their
// last ldmatrix of a stage; the producer (warp0 lane0) waits empty before
// re-arming full[s] + issuing the next bulk copy.  No per-iteration barriers.
// SMEM: [0,16K) B hi/lo; [16K,80K) A ring; sZ @81920; zbuf @82176;
//       mbars @83200 (full0,full1,B,empty0,empty1).
#define ATTN_SMEM 83456

__global__ __launch_bounds__(256, 2) void attn_fused_kernel(float* __restrict__ beta_out) {
    extern __shared__ __align__(1024) char dynsm[];
    uint32_t smem_base = smem_u32(dynsm);
    const uint32_t SB  = smem_base;             // B hi @0, lo @8192
    const uint32_t SA0 = smem_base + 16384;     // ring stage s at +s*32768
    float* sZ   = (float*)(dynsm + 81920);      // 64 floats
    float* zbuf = (float*)(dynsm + 82176);      // 4 x 64 floats
    const uint32_t MB_FULL0  = smem_base + 83200;
    const uint32_t MB_FULL1  = smem_base + 83208;
    const uint32_t MB_B      = smem_base + 83216;
    const uint32_t MB_EMPTY0 = smem_base + 83224;
    const uint32_t MB_EMPTY1 = smem_base + 83232;

    int b  = blockIdx.y;
    int j0 = blockIdx.x * 64;
    int tid = threadIdx.x;
    int lane = tid & 31, wid = tid >> 5;
    int wn = wid & 1, wm = wid >> 1;   // 4 m-groups of 32 rows, 2 n-groups of 32 cols

    const char* gBhi = (const char*)(d_gb_hi + ((size_t)b * NDIM + j0) * KDIM);
    const char* gBlo = (const char*)(d_gb_lo + ((size_t)b * NDIM + j0) * KDIM);
    const char* gAhi = (const char*)(d_fa_hi + (size_t)b * NDIM * KDIM);
    const char* gAlo = (const char*)(d_fa_lo + (size_t)b * NDIM * KDIM);

    if (tid == 0) {
        MBARRIER_INIT(MB_FULL0, 1);
        MBARRIER_INIT(MB_FULL1, 1);
        MBARRIER_INIT(MB_B, 1);
        MBARRIER_INIT(MB_EMPTY0, 8);
        MBARRIER_INIT(MB_EMPTY1, 8);
        FENCE_PROXY_ASYNC();
        MBARRIER_EXPECT_TX(MB_B, 16384);
        CP_BULK(SB,        gBhi, 8192, MB_B);
        CP_BULK(SB + 8192, gBlo, 8192, MB_B);
        MBARRIER_EXPECT_TX(MB_FULL0, 32768);
        CP_BULK(SA0,         gAhi, 16384, MB_FULL0);
        CP_BULK(SA0 + 16384, gAlo, 16384, MB_FULL0);
        MBARRIER_EXPECT_TX(MB_FULL1, 32768);
        CP_BULK(SA0 + 32768, gAhi + 16384, 16384, MB_FULL1);
        CP_BULK(SA0 + 49152, gAlo + 16384, 16384, MB_FULL1);
    }
    __syncthreads();
    mbar_wait_parity(MB_B, 0);

    uint32_t tB = SB, tBlo = SB + 8192;
    float zp0[4] = {0.f, 0.f, 0.f, 0.f};
    float zp1[4] = {0.f, 0.f, 0.f, 0.f};
    float* ob = beta_out + (size_t)b * NN;

    for (int n = 0; n < 64; n++) {
        int s = n & 1;
        uint32_t mb_full  = s ? MB_FULL1 : MB_FULL0;
        uint32_t mb_empty = s ? MB_EMPTY1 : MB_EMPTY0;
        uint32_t ph = (n >> 1) & 1;
        mbar_wait_parity(mb_full, ph);

        uint32_t tA = SA0 + s * 32768, tAlo = tA + 16384;
        float acc[2][4][4];
        #pragma unroll
        for (int mf = 0; mf < 2; mf++)
            #pragma unroll
            for (int nf = 0; nf < 4; nf++)
                #pragma unroll
                for (int e = 0; e < 4; e++) acc[mf][nf][e] = 0.f;

        #pragma unroll
        for (int ks = 0; ks < 4; ks++) {
            int kc = ks * 2;
            uint32_t ahi[2][4], alo[2][4], bhi[4][2], blo[4][2];
            #pragma unroll
            for (int mf = 0; mf < 2; mf++) ldA(tA, wm * 32 + mf * 16, kc, lane, ahi[mf]);
            #pragma unroll
            for (int nf = 0; nf < 4; nf++) ldB(tB, wn * 32 + nf * 8, kc, lane, bhi[nf]);
            #pragma unroll
            for (int mf = 0; mf < 2; mf++)
                #pragma unroll
                for (int nf = 0; nf < 4; nf++) mma_bf16(acc[mf][nf], ahi[mf], bhi[nf]);
            #pragma unroll
            for (int mf = 0; mf < 2; mf++) ldA(tAlo, wm * 32 + mf * 16, kc, lane, alo[mf]);
            #pragma unroll
            for (int mf = 0; mf < 2; mf++)
                #pragma unroll
                for (int nf = 0; nf < 4; nf++) mma_bf16(acc[mf][nf], alo[mf], bhi[nf]);
            #pragma unroll
            for (int nf = 0; nf < 4; nf++) ldB(tBlo, wn * 32 + nf * 8, kc, lane, blo[nf]);
            #pragma unroll
            for (int mf = 0; mf < 2; mf++)
                #pragma unroll
                for (int nf = 0; nf < 4; nf++) mma_bf16(acc[mf][nf], ahi[mf], blo[nf]);
        }

        // this warp is done reading ring stage s
        if (lane == 0) MBARRIER_ARRIVE(mb_empty);

        // producer: re-arm stage s for iteration n+2 once all warps released it
        if (wid == 0 && lane == 0 && n < 62) {
            mbar_wait_parity(mb_empty, ph);
            size_t t = (size_t)((n + 2) & 31) * 16384;
            MBARRIER_EXPECT_TX(mb_full, 32768);
            CP_BULK(tA,   gAhi + t, 16384, mb_full);
            CP_BULK(tAlo, gAlo + t, 16384, mb_full);
        }

        if (n < 32) {
            // phase 1: lane-local Z partials
            #pragma unroll
            for (int nf = 0; nf < 4; nf++) {
                float s0 = 0.f, s1 = 0.f;
                #pragma unroll
                for (int mf = 0; mf < 2; mf++) {
                    s0 += fast_exp(acc[mf][nf][0]) + fast_exp(acc[mf][nf][2]);
                    s1 += fast_exp(acc[mf][nf][1]) + fast_exp(acc[mf][nf][3]);
                }
                zp0[nf] += s0;
                zp1[nf] += s1;
            }
            if (n == 31) {
                // finalize Z: butterfly over the 8 row-groups, merge 4 wm groups
                #pragma unroll
                for (int nf = 0; nf < 4; nf++) {
                    #pragma unroll
                    for (int o = 4; o < 32; o <<= 1) {
                        zp0[nf] += __shfl_xor_sync(0xFFFFFFFFu, zp0[nf], o);
                        zp1[nf] += __shfl_xor_sync(0xFFFFFFFFu, zp1[nf], o);
                    }
                }
                if (lane < 4) {
                    #pragma unroll
                    for (int nf = 0; nf < 4; nf++) {
                        int cc = wn * 32 + nf * 8 + lane * 2;
                        zbuf[wm * 64 + cc]     = zp0[nf];
                        zbuf[wm * 64 + cc + 1] = zp1[nf];
                    }
                }
                __syncthreads();
                if (tid < 64)
                    sZ[tid] = 1.0f / (zbuf[tid] + zbuf[64 + tid] +
                                      zbuf[128 + tid] + zbuf[192 + tid]);
                __syncthreads();
            }
        } else {
            // phase 2: beta = exp(s)/Z (streaming stores), accumulate rowsum
            int i0 = (n - 32) * 128;
            float rs0[2], rs1[2];
            #pragma unroll
            for (int mf = 0; mf < 2; mf++) { rs0[mf] = 0.f; rs1[mf] = 0.f; }
            #pragma unroll
            for (int mf = 0; mf < 2; mf++) {
                int r = wm * 32 + mf * 16 + (lane >> 2);
                #pragma unroll
                for (int nf = 0; nf < 4; nf++) {
                    int cc = wn * 32 + nf * 8 + (lane & 3) * 2;
                    float iz0 = sZ[cc], iz1 = sZ[cc + 1];
                    float v0 = fast_exp(acc[mf][nf][0]) * iz0;
                    float v1 = fast_exp(acc[mf][nf][1]) * iz1;
                    float v2 = fast_exp(acc[mf][nf][2]) * iz0;
                    float v3 = fast_exp(acc[mf][nf][3]) * iz1;
                    __stcs((float2*)(ob + (size_t)(i0 + r) * NDIM + j0 + cc),
                           make_float2(v0, v1));
                    __stcs((float2*)(ob + (size_t)(i0 + r + 8) * NDIM + j0 + cc),
                           make_float2(v2, v3));
                    rs0[mf] += v0 + v1;
                    rs1[mf] += v2 + v3;
                }
            }
            #pragma unroll
            for (int mf = 0; mf < 2; mf++) {
                #pragma unroll
                for (int o = 1; o < 4; o <<= 1) {
                    rs0[mf] += __shfl_xor_sync(0xFFFFFFFFu, rs0[mf], o);
                    rs1[mf] += __shfl_xor_sync(0xFFFFFFFFu, rs1[mf], o);
                }
            }
            if ((lane & 3) == 0) {
                #pragma unroll
                for (int mf = 0; mf < 2; mf++) {
                    int r = wm * 32 + mf * 16 + (lane >> 2);
                    atomicAdd(&d_rowsum[b * NDIM + i0 + r], rs0[mf]);
                    atomicAdd(&d_rowsum[b * NDIM + i0 + r + 8], rs1[mf]);
                }
            }
        }
    }
}

// ---------------- pooled epilogue ----------------
__global__ __launch_bounds__(256) void pool1_kernel(const float* __restrict__ x) {
    int b = blockIdx.y;
    int cc = blockIdx.x * 8 + (threadIdx.x >> 5);
    int lane = threadIdx.x & 31;
    const float* xr = x + ((size_t)b * CDIM + cc) * NDIM;
    const float* rs = d_rowsum + b * NDIM;
    float ay = 0.f, ax = 0.f;
    for (int i = lane; i < NDIM; i += 32) {
        float xv = xr[i];
        ay += xv * rs[i];
        ax += xv;
    }
    ay = warp_sum(ay); ax = warp_sum(ax);
    if (lane == 0) {
        d_y[b * CDIM + cc]    = ay * (1.0f / NDIM);
        d_xbar[b * CDIM + cc] = ax * (1.0f / NDIM);
    }
}

__global__ __launch_bounds__(256) void pool2_kernel(const float* __restrict__ Wv,
                                                    const float* __restrict__ gamma,
                                                    float* __restrict__ out) {
    int b = blockIdx.y;
    int c = blockIdx.x * 8 + (threadIdx.x >> 5);
    int lane = threadIdx.x & 31;
    const float* wr = Wv + (size_t)c * CDIM;
    const float* yb = d_y + b * CDIM;
    float a = 0.f;
    for (int k = lane; k < CDIM; k += 32) a += wr[k] * yb[k];
    a = warp_sum(a);
    if (lane == 0) out[b * CDIM + c] = gamma[0] * a + d_xbar[b * CDIM + c];
}

// ---------------- launch ----------------
extern "C" void kernel_launch(void* const* d_in, const int* in_sizes, int n_in,
                              void* d_out, int out_size) {
    const float* x     = (const float*)d_in[0];
    const float* Wq    = (const float*)d_in[1];
    const float* Wk    = (const float*)d_in[2];
    const float* Wv    = (const float*)d_in[3];
    const float* gamma = (const float*)d_in[4];
    float* out    = (float*)d_out;
    float* pooled = out;                 // [B,C,1,1] = 2048 floats
    float* beta   = out + BATCH * CDIM;  // [B,N,N]

    cudaFuncSetAttribute(fg_kernel, cudaFuncAttributeMaxDynamicSharedMemorySize, FG_SMEM);
    cudaFuncSetAttribute(attn_fused_kernel, cudaFuncAttributeMaxDynamicSharedMemorySize,
                         ATTN_SMEM);

    wsplit_kernel<<<(128 * CDIM + 255) / 256, 256>>>(Wq, Wk);
    fg_kernel<<<dim3(32, BATCH), 256, FG_SMEM>>>(x);
    attn_fused_kernel<<<dim3(64, BATCH), 256, ATTN_SMEM>>>(beta);
    pool1_kernel<<<dim3(CDIM / 8, BATCH), 256>>>(x);
    pool2_kernel<<<dim3(CDIM / 8, BATCH), 256>>>(Wv, gamma, pooled);
}

// round 7
// speedup vs baseline: 1.1610x; 1.0264x over previous
#include <cuda_runtime.h>
#include <cuda_bf16.h>
#include <cstdint>
#include <cstddef>

#define BATCH 4
#define CDIM  512
#define KDIM  64
#define NDIM  4096
#define NN    ((size_t)NDIM * NDIM)

// ---------------- device scratch (no allocs allowed) ----------------
// f/g operand arrays are stored PRE-SWIZZLED (XOR-16B within each
// 128-row x 64-col tile; pattern depends only on row&7) so attention can
// bulk-copy them linearly.
__device__ __align__(128) __nv_bfloat16 d_fa_hi[BATCH * NDIM * KDIM]; // f, i-major
__device__ __align__(128) __nv_bfloat16 d_fa_lo[BATCH * NDIM * KDIM];
__device__ __align__(128) __nv_bfloat16 d_gb_hi[BATCH * NDIM * KDIM]; // g, j-major
__device__ __align__(128) __nv_bfloat16 d_gb_lo[BATCH * NDIM * KDIM];
__device__ __align__(16) __nv_bfloat16 d_w_hi[128 * CDIM];            // [Wq;Wk] split
__device__ __align__(16) __nv_bfloat16 d_w_lo[128 * CDIM];
__device__ float d_rowsum[BATCH * NDIM];  // row sums of beta
__device__ float d_y[BATCH * CDIM];
__device__ float d_xbar[BATCH * CDIM];

__device__ __forceinline__ float fast_exp(float x) {
    float y;
    asm("ex2.approx.ftz.f32 %0, %1;" : "=f"(y) : "f"(x * 1.4426950408889634f));
    return y;
}

__device__ __forceinline__ float warp_sum(float v) {
    #pragma unroll
    for (int o = 16; o; o >>= 1) v += __shfl_xor_sync(0xFFFFFFFFu, v, o);
    return v;
}

__device__ __forceinline__ uint32_t smem_u32(const void* p) {
    uint32_t a;
    asm("{ .reg .u64 t; cvta.to.shared.u64 t, %1; cvt.u32.u64 %0, t; }"
        : "=r"(a) : "l"(p));
    return a;
}

// hi bf16x2 of (v0,v1) by mantissa truncation (exact bf16 bits)
__device__ __forceinline__ uint32_t pack_hi2(float v0, float v1) {
    uint32_t r;
    asm("prmt.b32 %0, %1, %2, 0x7632;"
        : "=r"(r) : "r"(__float_as_uint(v0)), "r"(__float_as_uint(v1)));
    return r;
}
// residual lo bf16x2: lo_k = v_k - trunc_bf16(v_k), rounded to bf16
__device__ __forceinline__ uint32_t pack_lo2(float v0, float v1) {
    float l0 = v0 - __uint_as_float(__float_as_uint(v0) & 0xFFFF0000u);
    float l1 = v1 - __uint_as_float(__float_as_uint(v1) & 0xFFFF0000u);
    uint32_t r;
    asm("cvt.rn.bf16x2.f32 %0, %1, %2;" : "=r"(r) : "f"(l1), "f"(l0));
    return r;
}

// A fragment (m16 x k16) via ldmatrix x4 from m-major SW-swizzled [rows][64] bf16 tile
__device__ __forceinline__ void ldA(uint32_t tile, int rbase, int kc, int lane, uint32_t* a) {
    int r = rbase + (lane & 15);
    int c = kc + (lane >> 4);
    uint32_t addr = tile + r * 128 + ((c ^ (r & 7)) << 4);
    asm volatile("ldmatrix.sync.aligned.m8n8.x4.shared.b16 {%0,%1,%2,%3}, [%4];"
                 : "=r"(a[0]), "=r"(a[1]), "=r"(a[2]), "=r"(a[3]) : "r"(addr));
}

// TWO B fragments (two adjacent n8 x k16) via one ldmatrix x4:
// lanes 0-15 address rows rbase..rbase+7 (both k-chunks), lanes 16-31 rows +8..+15.
// Result: b01[0],b01[1] = frag nf; b01[2],b01[3] = frag nf+1.
__device__ __forceinline__ void ldB4(uint32_t tile, int rbase, int kc, int lane, uint32_t* b01) {
    int r = rbase + ((lane >> 1) & 8) + (lane & 7);
    int c = kc + ((lane >> 3) & 1);
    uint32_t addr = tile + r * 128 + ((c ^ (r & 7)) << 4);
    asm volatile("ldmatrix.sync.aligned.m8n8.x4.shared.b16 {%0,%1,%2,%3}, [%4];"
                 : "=r"(b01[0]), "=r"(b01[1]), "=r"(b01[2]), "=r"(b01[3]) : "r"(addr));
}

__device__ __forceinline__ void mma_bf16(float* acc, const uint32_t* a, const uint32_t* bb) {
    asm volatile(
        "mma.sync.aligned.m16n8k16.row.col.f32.bf16.bf16.f32 "
        "{%0,%1,%2,%3}, {%4,%5,%6,%7}, {%8,%9}, {%0,%1,%2,%3};"
        : "+f"(acc[0]), "+f"(acc[1]), "+f"(acc[2]), "+f"(acc[3])
        : "r"(a[0]), "r"(a[1]), "r"(a[2]), "r"(a[3]), "r"(bb[0]), "r"(bb[1]));
}

// ---------------- mbarrier + bulk-copy helpers (sm_90 baseline PTX) ----------------
#define MBARRIER_INIT(mbar, count) \
    asm volatile("mbarrier.init.shared.b64 [%0], %1;" \
                 :: "r"((uint32_t)(mbar)), "r"((uint32_t)(count)) : "memory")
#define MBARRIER_EXPECT_TX(mbar, bytes) \
    asm volatile("mbarrier.arrive.expect_tx.shared.b64 _, [%0], %1;" \
                 :: "r"((uint32_t)(mbar)), "r"((uint32_t)(bytes)) : "memory")
#define MBARRIER_ARRIVE(mbar) \
    asm volatile("mbarrier.arrive.shared.b64 _, [%0];" \
                 :: "r"((uint32_t)(mbar)) : "memory")
#define FENCE_PROXY_ASYNC() \
    asm volatile("fence.proxy.async.shared::cta;" ::: "memory")
#define CP_BULK(dst_smem, src_gmem, bytes, mbar) \
    asm volatile("cp.async.bulk.shared::cta.global.mbarrier::complete_tx::bytes " \
                 "[%0], [%1], %2, [%3];" \
                 :: "r"((uint32_t)(dst_smem)), "l"(src_gmem), "r"((uint32_t)(bytes)), \
                    "r"((uint32_t)(mbar)) : "memory")

__device__ __forceinline__ void mbar_wait_parity(uint32_t mbar, uint32_t parity) {
    uint32_t done;
    asm volatile(
        "{\n\t.reg .pred p;\n\t"
        "mbarrier.try_wait.parity.acquire.cta.shared::cta.b64 p, [%1], %2;\n\t"
        "selp.b32 %0, 1, 0, p;\n\t}"
        : "=r"(done) : "r"(mbar), "r"(parity) : "memory");
    if (!done) {
        asm volatile(
            "{\n\t.reg .pred P1;\n\t"
            "WAIT_LOOP_%=:\n\t"
            "mbarrier.try_wait.parity.acquire.cta.shared::cta.b64 P1, [%0], %1, 0x989680;\n\t"
            "@P1 bra.uni WAIT_DONE_%=;\n\t"
            "bra.uni WAIT_LOOP_%=;\n\t"
            "WAIT_DONE_%=:\n\t}"
            :: "r"(mbar), "r"(parity) : "memory");
    }
}

// ---------------- W split prep + rowsum zero ----------------
__global__ __launch_bounds__(256) void wsplit_kernel(const float* __restrict__ Wq,
                                                     const float* __restrict__ Wk) {
    int idx = blockIdx.x * blockDim.x + threadIdx.x;
    if (idx < BATCH * NDIM) d_rowsum[idx] = 0.f;
    if (idx >= 128 * CDIM) return;
    int m = idx >> 9;
    int c = idx & 511;
    float w = (m < 64) ? Wq[m * CDIM + c] : Wk[(m - 64) * CDIM + c];
    __nv_bfloat16 hi = __float2bfloat16(w);
    d_w_hi[idx] = hi;
    d_w_lo[idx] = __float2bfloat16(w - __bfloat162float(hi));
}

// ---------------- FG: [f;g] = [Wq;Wk] @ x[b] via bf16x3 mma.sync ----------------
#define FG_SMEM (128 * 132 * 4)  // 67584

__global__ __launch_bounds__(256) void fg_kernel(const float* __restrict__ x) {
    extern __shared__ __align__(1024) char dynsm[];
    uint32_t smem_base = smem_u32(dynsm);
    uint4* sWhi = (uint4*)(dynsm);
    uint4* sWlo = (uint4*)(dynsm + 16384);
    uint4* sXhi = (uint4*)(dynsm + 32768);
    uint4* sXlo = (uint4*)(dynsm + 49152);
    float* S = (float*)dynsm;  // [128][132] alias after mainloop

    int b = blockIdx.y;
    int i0 = blockIdx.x * 128;
    int tid = threadIdx.x;
    int lane = tid & 31, wid = tid >> 5;
    int wm = wid >> 2, wn = wid & 3;
    const float* xb = x + (size_t)b * CDIM * NDIM;

    float acc[4][4][4];
    #pragma unroll
    for (int mf = 0; mf < 4; mf++)
        #pragma unroll
        for (int nf = 0; nf < 4; nf++)
            #pragma unroll
            for (int e = 0; e < 4; e++) acc[mf][nf][e] = 0.f;

    for (int c0 = 0; c0 < CDIM; c0 += 64) {
        #pragma unroll
        for (int t = 0; t < 4; t++) {
            int idx = tid + t * 256;
            int m = idx >> 3, ch = idx & 7;
            int soff = m * 8 + (ch ^ (m & 7));
            sWhi[soff] = ((const uint4*)(d_w_hi + (size_t)m * CDIM + c0))[ch];
            sWlo[soff] = ((const uint4*)(d_w_lo + (size_t)m * CDIM + c0))[ch];
        }
        #pragma unroll
        for (int t = 0; t < 4; t++) {
            int idx = tid + t * 256;
            int n = idx & 127, oct = idx >> 7;
            const float* src = xb + (size_t)(c0 + oct * 8) * NDIM + i0 + n;
            float v[8];
            #pragma unroll
            for (int j = 0; j < 8; j++) v[j] = src[(size_t)j * NDIM];
            uint4 hw, lw;
            hw.x = pack_hi2(v[0], v[1]); lw.x = pack_lo2(v[0], v[1]);
            hw.y = pack_hi2(v[2], v[3]); lw.y = pack_lo2(v[2], v[3]);
            hw.z = pack_hi2(v[4], v[5]); lw.z = pack_lo2(v[4], v[5]);
            hw.w = pack_hi2(v[6], v[7]); lw.w = pack_lo2(v[6], v[7]);
            int soff = n * 8 + (oct ^ (n & 7));
            sXhi[soff] = hw;
            sXlo[soff] = lw;
        }
        __syncthreads();

        uint32_t tA = smem_base, tAlo = smem_base + 16384;
        uint32_t tB = smem_base + 32768, tBlo = smem_base + 49152;
        #pragma unroll
        for (int ks = 0; ks < 4; ks++) {
            int kc = ks * 2;
            uint32_t ahi[4][4], alo[4][4], bhi[4][2], blo[4][2];
            #pragma unroll
            for (int mf = 0; mf < 4; mf++) ldA(tA, wm * 64 + mf * 16, kc, lane, ahi[mf]);
            ldB4(tB, wn * 32,      kc, lane, &bhi[0][0]);
            ldB4(tB, wn * 32 + 16, kc, lane, &bhi[2][0]);
            #pragma unroll
            for (int mf = 0; mf < 4; mf++)
                #pragma unroll
                for (int nf = 0; nf < 4; nf++) mma_bf16(acc[mf][nf], ahi[mf], bhi[nf]);
            #pragma unroll
            for (int mf = 0; mf < 4; mf++) ldA(tAlo, wm * 64 + mf * 16, kc, lane, alo[mf]);
            #pragma unroll
            for (int mf = 0; mf < 4; mf++)
                #pragma unroll
                for (int nf = 0; nf < 4; nf++) mma_bf16(acc[mf][nf], alo[mf], bhi[nf]);
            ldB4(tBlo, wn * 32,      kc, lane, &blo[0][0]);
            ldB4(tBlo, wn * 32 + 16, kc, lane, &blo[2][0]);
            #pragma unroll
            for (int mf = 0; mf < 4; mf++)
                #pragma unroll
                for (int nf = 0; nf < 4; nf++) mma_bf16(acc[mf][nf], ahi[mf], blo[nf]);
        }
        __syncthreads();
    }

    #pragma unroll
    for (int mf = 0; mf < 4; mf++)
        #pragma unroll
        for (int nf = 0; nf < 4; nf++) {
            int r = wm * 64 + mf * 16 + (lane >> 2);
            int cc = wn * 32 + nf * 8 + (lane & 3) * 2;
            S[r * 132 + cc]           = acc[mf][nf][0];
            S[r * 132 + cc + 1]       = acc[mf][nf][1];
            S[(r + 8) * 132 + cc]     = acc[mf][nf][2];
            S[(r + 8) * 132 + cc + 1] = acc[mf][nf][3];
        }
    __syncthreads();

    // write split bf16 PRE-SWIZZLED: chunk index XORed with (row & 7)
    int arr = lane >> 3, chunk = lane & 7;
    int mbase = (arr >= 2 ? 64 : 0) + chunk * 8;
    __nv_bfloat16* dst = (arr == 0) ? d_fa_hi : (arr == 1) ? d_fa_lo
                       : (arr == 2) ? d_gb_hi : d_gb_lo;
    bool lo_arr = (arr & 1);
    for (int r = wid; r < 128; r += 8) {
        uint4 wv;
        float v0, v1;
        v0 = S[(mbase + 0) * 132 + r]; v1 = S[(mbase + 1) * 132 + r];
        wv.x = lo_arr ? pack_lo2(v0, v1) : pack_hi2(v0, v1);
        v0 = S[(mbase + 2) * 132 + r]; v1 = S[(mbase + 3) * 132 + r];
        wv.y = lo_arr ? pack_lo2(v0, v1) : pack_hi2(v0, v1);
        v0 = S[(mbase + 4) * 132 + r]; v1 = S[(mbase + 5) * 132 + r];
        wv.z = lo_arr ? pack_lo2(v0, v1) : pack_hi2(v0, v1);
        v0 = S[(mbase + 6) * 132 + r]; v1 = S[(mbase + 7) * 132 + r];
        wv.w = lo_arr ? pack_lo2(v0, v1) : pack_hi2(v0, v1);
        int chs = chunk ^ (r & 7);
        *(uint4*)(dst + ((size_t)b * NDIM + i0 + r) * KDIM + chs * 8) = wv;
    }
}

// ---------------- fused attention: one CTA per (b, 64-j strip), 2 CTAs/SM -------
// Tile 128(i) x 64(j).  Phase 1 (i-tiles 0..31): Z[j] in registers.
// Phase 2: recompute, beta = exp(s)/Z, rowsum.  B resident; A 2-stage bulk ring.
// Warp-desynchronized ring: consumers arrive on empty[s] (count=8) after their
// last ldmatrix of a stage; producer (warp0 lane0) waits empty before re-arming.
// SMEM: [0,16K) B hi/lo; [16K,80K) A ring; sZ @81920; zbuf @82176;
//       mbars @83200 (full0,full1,B,empty0,empty1).
#define ATTN_SMEM 83456

__global__ __launch_bounds__(256, 2) void attn_fused_kernel(float* __restrict__ beta_out) {
    extern __shared__ __align__(1024) char dynsm[];
    uint32_t smem_base = smem_u32(dynsm);
    const uint32_t SB  = smem_base;             // B hi @0, lo @8192
    const uint32_t SA0 = smem_base + 16384;     // ring stage s at +s*32768
    float* sZ   = (float*)(dynsm + 81920);      // 64 floats
    float* zbuf = (float*)(dynsm + 82176);      // 4 x 64 floats
    const uint32_t MB_FULL0  = smem_base + 83200;
    const uint32_t MB_FULL1  = smem_base + 83208;
    const uint32_t MB_B      = smem_base + 83216;
    const uint32_t MB_EMPTY0 = smem_base + 83224;
    const uint32_t MB_EMPTY1 = smem_base + 83232;

    int b  = blockIdx.y;
    int j0 = blockIdx.x * 64;
    int tid = threadIdx.x;
    int lane = tid & 31, wid = tid >> 5;
    int wn = wid & 1, wm = wid >> 1;   // 4 m-groups of 32 rows, 2 n-groups of 32 cols

    const char* gBhi = (const char*)(d_gb_hi + ((size_t)b * NDIM + j0) * KDIM);
    const char* gBlo = (const char*)(d_gb_lo + ((size_t)b * NDIM + j0) * KDIM);
    const char* gAhi = (const char*)(d_fa_hi + (size_t)b * NDIM * KDIM);
    const char* gAlo = (const char*)(d_fa_lo + (size_t)b * NDIM * KDIM);

    if (tid == 0) {
        MBARRIER_INIT(MB_FULL0, 1);
        MBARRIER_INIT(MB_FULL1, 1);
        MBARRIER_INIT(MB_B, 1);
        MBARRIER_INIT(MB_EMPTY0, 8);
        MBARRIER_INIT(MB_EMPTY1, 8);
        FENCE_PROXY_ASYNC();
        MBARRIER_EXPECT_TX(MB_B, 16384);
        CP_BULK(SB,        gBhi, 8192, MB_B);
        CP_BULK(SB + 8192, gBlo, 8192, MB_B);
        MBARRIER_EXPECT_TX(MB_FULL0, 32768);
        CP_BULK(SA0,         gAhi, 16384, MB_FULL0);
        CP_BULK(SA0 + 16384, gAlo, 16384, MB_FULL0);
        MBARRIER_EXPECT_TX(MB_FULL1, 32768);
        CP_BULK(SA0 + 32768, gAhi + 16384, 16384, MB_FULL1);
        CP_BULK(SA0 + 49152, gAlo + 16384, 16384, MB_FULL1);
    }
    __syncthreads();
    mbar_wait_parity(MB_B, 0);

    uint32_t tB = SB, tBlo = SB + 8192;
    float zp0[4] = {0.f, 0.f, 0.f, 0.f};
    float zp1[4] = {0.f, 0.f, 0.f, 0.f};
    float* ob = beta_out + (size_t)b * NN;

    for (int n = 0; n < 64; n++) {
        int s = n & 1;
        uint32_t mb_full  = s ? MB_FULL1 : MB_FULL0;
        uint32_t mb_empty = s ? MB_EMPTY1 : MB_EMPTY0;
        uint32_t ph = (n >> 1) & 1;
        mbar_wait_parity(mb_full, ph);

        uint32_t tA = SA0 + s * 32768, tAlo = tA + 16384;
        float acc[2][4][4];
        #pragma unroll
        for (int mf = 0; mf < 2; mf++)
            #pragma unroll
            for (int nf = 0; nf < 4; nf++)
                #pragma unroll
                for (int e = 0; e < 4; e++) acc[mf][nf][e] = 0.f;

        #pragma unroll
        for (int ks = 0; ks < 4; ks++) {
            int kc = ks * 2;
            uint32_t ahi[2][4], alo[2][4], bhi[4][2], blo[4][2];
            #pragma unroll
            for (int mf = 0; mf < 2; mf++) ldA(tA, wm * 32 + mf * 16, kc, lane, ahi[mf]);
            ldB4(tB, wn * 32,      kc, lane, &bhi[0][0]);
            ldB4(tB, wn * 32 + 16, kc, lane, &bhi[2][0]);
            #pragma unroll
            for (int mf = 0; mf < 2; mf++)
                #pragma unroll
                for (int nf = 0; nf < 4; nf++) mma_bf16(acc[mf][nf], ahi[mf], bhi[nf]);
            #pragma unroll
            for (int mf = 0; mf < 2; mf++) ldA(tAlo, wm * 32 + mf * 16, kc, lane, alo[mf]);
            #pragma unroll
            for (int mf = 0; mf < 2; mf++)
                #pragma unroll
                for (int nf = 0; nf < 4; nf++) mma_bf16(acc[mf][nf], alo[mf], bhi[nf]);
            ldB4(tBlo, wn * 32,      kc, lane, &blo[0][0]);
            ldB4(tBlo, wn * 32 + 16, kc, lane, &blo[2][0]);
            #pragma unroll
            for (int mf = 0; mf < 2; mf++)
                #pragma unroll
                for (int nf = 0; nf < 4; nf++) mma_bf16(acc[mf][nf], ahi[mf], blo[nf]);
        }

        // this warp is done reading ring stage s
        if (lane == 0) MBARRIER_ARRIVE(mb_empty);

        // producer: re-arm stage s for iteration n+2 once all warps released it
        if (wid == 0 && lane == 0 && n < 62) {
            mbar_wait_parity(mb_empty, ph);
            size_t t = (size_t)((n + 2) & 31) * 16384;
            MBARRIER_EXPECT_TX(mb_full, 32768);
            CP_BULK(tA,   gAhi + t, 16384, mb_full);
            CP_BULK(tAlo, gAlo + t, 16384, mb_full);
        }

        if (n < 32) {
            // phase 1: lane-local Z partials
            #pragma unroll
            for (int nf = 0; nf < 4; nf++) {
                float s0 = 0.f, s1 = 0.f;
                #pragma unroll
                for (int mf = 0; mf < 2; mf++) {
                    s0 += fast_exp(acc[mf][nf][0]) + fast_exp(acc[mf][nf][2]);
                    s1 += fast_exp(acc[mf][nf][1]) + fast_exp(acc[mf][nf][3]);
                }
                zp0[nf] += s0;
                zp1[nf] += s1;
            }
            if (n == 31) {
                // finalize Z: butterfly over the 8 row-groups, merge 4 wm groups
                #pragma unroll
                for (int nf = 0; nf < 4; nf++) {
                    #pragma unroll
                    for (int o = 4; o < 32; o <<= 1) {
                        zp0[nf] += __shfl_xor_sync(0xFFFFFFFFu, zp0[nf], o);
                        zp1[nf] += __shfl_xor_sync(0xFFFFFFFFu, zp1[nf], o);
                    }
                }
                if (lane < 4) {
                    #pragma unroll
                    for (int nf = 0; nf < 4; nf++) {
                        int cc = wn * 32 + nf * 8 + lane * 2;
                        zbuf[wm * 64 + cc]     = zp0[nf];
                        zbuf[wm * 64 + cc + 1] = zp1[nf];
                    }
                }
                __syncthreads();
                if (tid < 64)
                    sZ[tid] = 1.0f / (zbuf[tid] + zbuf[64 + tid] +
                                      zbuf[128 + tid] + zbuf[192 + tid]);
                __syncthreads();
            }
        } else {
            // phase 2: beta = exp(s)/Z (streaming stores), accumulate rowsum
            int i0 = (n - 32) * 128;
            float rs0[2], rs1[2];
            #pragma unroll
            for (int mf = 0; mf < 2; mf++) { rs0[mf] = 0.f; rs1[mf] = 0.f; }
            #pragma unroll
            for (int mf = 0; mf < 2; mf++) {
                int r = wm * 32 + mf * 16 + (lane >> 2);
                #pragma unroll
                for (int nf = 0; nf < 4; nf++) {
                    int cc = wn * 32 + nf * 8 + (lane & 3) * 2;
                    float iz0 = sZ[cc], iz1 = sZ[cc + 1];
                    float v0 = fast_exp(acc[mf][nf][0]) * iz0;
                    float v1 = fast_exp(acc[mf][nf][1]) * iz1;
                    float v2 = fast_exp(acc[mf][nf][2]) * iz0;
                    float v3 = fast_exp(acc[mf][nf][3]) * iz1;
                    __stcs((float2*)(ob + (size_t)(i0 + r) * NDIM + j0 + cc),
                           make_float2(v0, v1));
                    __stcs((float2*)(ob + (size_t)(i0 + r + 8) * NDIM + j0 + cc),
                           make_float2(v2, v3));
                    rs0[mf] += v0 + v1;
                    rs1[mf] += v2 + v3;
                }
            }
            #pragma unroll
            for (int mf = 0; mf < 2; mf++) {
                #pragma unroll
                for (int o = 1; o < 4; o <<= 1) {
                    rs0[mf] += __shfl_xor_sync(0xFFFFFFFFu, rs0[mf], o);
                    rs1[mf] += __shfl_xor_sync(0xFFFFFFFFu, rs1[mf], o);
                }
            }
            if ((lane & 3) == 0) {
                #pragma unroll
                for (int mf = 0; mf < 2; mf++) {
                    int r = wm * 32 + mf * 16 + (lane >> 2);
                    atomicAdd(&d_rowsum[b * NDIM + i0 + r], rs0[mf]);
                    atomicAdd(&d_rowsum[b * NDIM + i0 + r + 8], rs1[mf]);
                }
            }
        }
    }
}

// ---------------- pooled epilogue ----------------
__global__ __launch_bounds__(256) void pool1_kernel(const float* __restrict__ x) {
    int b = blockIdx.y;
    int cc = blockIdx.x * 8 + (threadIdx.x >> 5);
    int lane = threadIdx.x & 31;
    const float4* xr = (const float4*)(x + ((size_t)b * CDIM + cc) * NDIM);
    const float4* rs = (const float4*)(d_rowsum + b * NDIM);
    float ay = 0.f, ax = 0.f;
    #pragma unroll 4
    for (int i = lane; i < NDIM / 4; i += 32) {
        float4 xv = xr[i];
        float4 rv = rs[i];
        ay += xv.x * rv.x + xv.y * rv.y + xv.z * rv.z + xv.w * rv.w;
        ax += xv.x + xv.y + xv.z + xv.w;
    }
    ay = warp_sum(ay); ax = warp_sum(ax);
    if (lane == 0) {
        d_y[b * CDIM + cc]    = ay * (1.0f / NDIM);
        d_xbar[b * CDIM + cc] = ax * (1.0f / NDIM);
    }
}

__global__ __launch_bounds__(256) void pool2_kernel(const float* __restrict__ Wv,
                                                    const float* __restrict__ gamma,
                                                    float* __restrict__ out) {
    int b = blockIdx.y;
    int c = blockIdx.x * 8 + (threadIdx.x >> 5);
    int lane = threadIdx.x & 31;
    const float* wr = Wv + (size_t)c * CDIM;
    const float* yb = d_y + b * CDIM;
    float a = 0.f;
    for (int k = lane; k < CDIM; k += 32) a += wr[k] * yb[k];
    a = warp_sum(a);
    if (lane == 0) out[b * CDIM + c] = gamma[0] * a + d_xbar[b * CDIM + c];
}

// ---------------- launch ----------------
extern "C" void kernel_launch(void* const* d_in, const int* in_sizes, int n_in,
                              void* d_out, int out_size) {
    const float* x     = (const float*)d_in[0];
    const float* Wq    = (const float*)d_in[1];
    const float* Wk    = (const float*)d_in[2];
    const float* Wv    = (const float*)d_in[3];
    const float* gamma = (const float*)d_in[4];
    float* out    = (float*)d_out;
    float* pooled = out;                 // [B,C,1,1] = 2048 floats
    float* beta   = out + BATCH * CDIM;  // [B,N,N]

    cudaFuncSetAttribute(fg_kernel, cudaFuncAttributeMaxDynamicSharedMemorySize, FG_SMEM);
    cudaFuncSetAttribute(attn_fused_kernel, cudaFuncAttributeMaxDynamicSharedMemorySize,
                         ATTN_SMEM);

    wsplit_kernel<<<(128 * CDIM + 255) / 256, 256>>>(Wq, Wk);
    fg_kernel<<<dim3(32, BATCH), 256, FG_SMEM>>>(x);
    attn_fused_kernel<<<dim3(64, BATCH), 256, ATTN_SMEM>>>(beta);
    pool1_kernel<<<dim3(CDIM / 8, BATCH), 256>>>(x);
    pool2_kernel<<<dim3(CDIM / 8, BATCH), 256>>>(Wv, gamma, pooled);
}

// round 9
// speedup vs baseline: 1.2789x; 1.1015x over previous
#include <cuda_runtime.h>
#include <cuda_bf16.h>
#include <cstdint>
#include <cstddef>

#define BATCH 4
#define CDIM  512
#define KDIM  64
#define NDIM  4096
#define NN    ((size_t)NDIM * NDIM)

// ---------------- device scratch (no allocs allowed) ----------------
// f/g operand arrays are stored PRE-SWIZZLED (XOR-16B within each
// 128-row x 64-col tile; pattern depends only on row&7) so attention can
// bulk-copy them linearly.  f is additionally pre-scaled by log2(e).
__device__ __align__(128) __nv_bfloat16 d_fa_hi[BATCH * NDIM * KDIM]; // f, i-major
__device__ __align__(128) __nv_bfloat16 d_fa_lo[BATCH * NDIM * KDIM];
__device__ __align__(128) __nv_bfloat16 d_gb_hi[BATCH * NDIM * KDIM]; // g, j-major
__device__ __align__(128) __nv_bfloat16 d_gb_lo[BATCH * NDIM * KDIM];
__device__ __align__(16) __nv_bfloat16 d_w_hi[128 * CDIM];            // [Wq*L2E;Wk] split
__device__ __align__(16) __nv_bfloat16 d_w_lo[128 * CDIM];
__device__ float d_Z[BATCH * NDIM];       // column sums of 2^s'
__device__ float d_rowsum[BATCH * NDIM];  // row sums of beta
__device__ float d_y[BATCH * CDIM];
__device__ float d_xbar[BATCH * CDIM];

// 2^x  (operands pre-scaled by log2 e upstream)
__device__ __forceinline__ float fast_exp2(float x) {
    float y;
    asm("ex2.approx.ftz.f32 %0, %1;" : "=f"(y) : "f"(x));
    return y;
}

__device__ __forceinline__ float warp_sum(float v) {
    #pragma unroll
    for (int o = 16; o; o >>= 1) v += __shfl_xor_sync(0xFFFFFFFFu, v, o);
    return v;
}

__device__ __forceinline__ uint32_t smem_u32(const void* p) {
    uint32_t a;
    asm("{ .reg .u64 t; cvta.to.shared.u64 t, %1; cvt.u32.u64 %0, t; }"
        : "=r"(a) : "l"(p));
    return a;
}

// hi bf16x2 of (v0,v1) by mantissa truncation (exact bf16 bits)
__device__ __forceinline__ uint32_t pack_hi2(float v0, float v1) {
    uint32_t r;
    asm("prmt.b32 %0, %1, %2, 0x7632;"
        : "=r"(r) : "r"(__float_as_uint(v0)), "r"(__float_as_uint(v1)));
    return r;
}
// residual lo bf16x2: lo_k = v_k - trunc_bf16(v_k), rounded to bf16
__device__ __forceinline__ uint32_t pack_lo2(float v0, float v1) {
    float l0 = v0 - __uint_as_float(__float_as_uint(v0) & 0xFFFF0000u);
    float l1 = v1 - __uint_as_float(__float_as_uint(v1) & 0xFFFF0000u);
    uint32_t r;
    asm("cvt.rn.bf16x2.f32 %0, %1, %2;" : "=r"(r) : "f"(l1), "f"(l0));
    return r;
}

// A fragment (m16 x k16) via ldmatrix x4 from m-major SW-swizzled [rows][64] bf16 tile
__device__ __forceinline__ void ldA(uint32_t tile, int rbase, int kc, int lane, uint32_t* a) {
    int r = rbase + (lane & 15);
    int c = kc + (lane >> 4);
    uint32_t addr = tile + r * 128 + ((c ^ (r & 7)) << 4);
    asm volatile("ldmatrix.sync.aligned.m8n8.x4.shared.b16 {%0,%1,%2,%3}, [%4];"
                 : "=r"(a[0]), "=r"(a[1]), "=r"(a[2]), "=r"(a[3]) : "r"(addr));
}

// TWO B fragments (two adjacent n8 x k16) via one ldmatrix x4
__device__ __forceinline__ void ldB4(uint32_t tile, int rbase, int kc, int lane, uint32_t* b01) {
    int r = rbase + ((lane >> 1) & 8) + (lane & 7);
    int c = kc + ((lane >> 3) & 1);
    uint32_t addr = tile + r * 128 + ((c ^ (r & 7)) << 4);
    asm volatile("ldmatrix.sync.aligned.m8n8.x4.shared.b16 {%0,%1,%2,%3}, [%4];"
                 : "=r"(b01[0]), "=r"(b01[1]), "=r"(b01[2]), "=r"(b01[3]) : "r"(addr));
}

__device__ __forceinline__ void mma_bf16(float* acc, const uint32_t* a, const uint32_t* bb) {
    asm volatile(
        "mma.sync.aligned.m16n8k16.row.col.f32.bf16.bf16.f32 "
        "{%0,%1,%2,%3}, {%4,%5,%6,%7}, {%8,%9}, {%0,%1,%2,%3};"
        : "+f"(acc[0]), "+f"(acc[1]), "+f"(acc[2]), "+f"(acc[3])
        : "r"(a[0]), "r"(a[1]), "r"(a[2]), "r"(a[3]), "r"(bb[0]), "r"(bb[1]));
}

// ---------------- mbarrier + bulk-copy helpers (sm_90 baseline PTX) ----------------
#define MBARRIER_INIT(mbar, count) \
    asm volatile("mbarrier.init.shared.b64 [%0], %1;" \
                 :: "r"((uint32_t)(mbar)), "r"((uint32_t)(count)) : "memory")
#define MBARRIER_EXPECT_TX(mbar, bytes) \
    asm volatile("mbarrier.arrive.expect_tx.shared.b64 _, [%0], %1;" \
                 :: "r"((uint32_t)(mbar)), "r"((uint32_t)(bytes)) : "memory")
#define FENCE_PROXY_ASYNC() \
    asm volatile("fence.proxy.async.shared::cta;" ::: "memory")
#define CP_BULK(dst_smem, src_gmem, bytes, mbar) \
    asm volatile("cp.async.bulk.shared::cta.global.mbarrier::complete_tx::bytes " \
                 "[%0], [%1], %2, [%3];" \
                 :: "r"((uint32_t)(dst_smem)), "l"(src_gmem), "r"((uint32_t)(bytes)), \
                    "r"((uint32_t)(mbar)) : "memory")

__device__ __forceinline__ void mbar_wait_parity(uint32_t mbar, uint32_t parity) {
    uint32_t done;
    asm volatile(
        "{\n\t.reg .pred p;\n\t"
        "mbarrier.try_wait.parity.acquire.cta.shared::cta.b64 p, [%1], %2;\n\t"
        "selp.b32 %0, 1, 0, p;\n\t}"
        : "=r"(done) : "r"(mbar), "r"(parity) : "memory");
    if (!done) {
        asm volatile(
            "{\n\t.reg .pred P1;\n\t"
            "WAIT_LOOP_%=:\n\t"
            "mbarrier.try_wait.parity.acquire.cta.shared::cta.b64 P1, [%0], %1, 0x989680;\n\t"
            "@P1 bra.uni WAIT_DONE_%=;\n\t"
            "bra.uni WAIT_LOOP_%=;\n\t"
            "WAIT_DONE_%=:\n\t}"
            :: "r"(mbar), "r"(parity) : "memory");
    }
}

// ---------------- W split prep + Z/rowsum zero ----------------
// Wq rows are pre-scaled by log2(e) so softmax uses bare ex2.
__global__ __launch_bounds__(256) void wsplit_kernel(const float* __restrict__ Wq,
                                                     const float* __restrict__ Wk) {
    int idx = blockIdx.x * blockDim.x + threadIdx.x;
    if (idx < BATCH * NDIM) { d_rowsum[idx] = 0.f; d_Z[idx] = 0.f; }
    if (idx >= 128 * CDIM) return;
    int m = idx >> 9;
    int c = idx & 511;
    float w = (m < 64) ? Wq[m * CDIM + c] * 1.4426950408889634f
                       : Wk[(m - 64) * CDIM + c];
    __nv_bfloat16 hi = __float2bfloat16(w);
    d_w_hi[idx] = hi;
    d_w_lo[idx] = __float2bfloat16(w - __bfloat162float(hi));
}

// ---------------- FG: [f;g] = [Wq*L2E;Wk] @ x[b] via bf16x3 mma.sync ----------------
#define FG_SMEM (128 * 132 * 4)  // 67584

__global__ __launch_bounds__(256) void fg_kernel(const float* __restrict__ x) {
    extern __shared__ __align__(1024) char dynsm[];
    uint32_t smem_base = smem_u32(dynsm);
    uint4* sWhi = (uint4*)(dynsm);
    uint4* sWlo = (uint4*)(dynsm + 16384);
    uint4* sXhi = (uint4*)(dynsm + 32768);
    uint4* sXlo = (uint4*)(dynsm + 49152);
    float* S = (float*)dynsm;  // [128][132] alias after mainloop

    int b = blockIdx.y;
    int i0 = blockIdx.x * 128;
    int tid = threadIdx.x;
    int lane = tid & 31, wid = tid >> 5;
    int wm = wid >> 2, wn = wid & 3;
    const float* xb = x + (size_t)b * CDIM * NDIM;

    float acc[4][4][4];
    #pragma unroll
    for (int mf = 0; mf < 4; mf++)
        #pragma unroll
        for (int nf = 0; nf < 4; nf++)
            #pragma unroll
            for (int e = 0; e < 4; e++) acc[mf][nf][e] = 0.f;

    for (int c0 = 0; c0 < CDIM; c0 += 64) {
        #pragma unroll
        for (int t = 0; t < 4; t++) {
            int idx = tid + t * 256;
            int m = idx >> 3, ch = idx & 7;
            int soff = m * 8 + (ch ^ (m & 7));
            sWhi[soff] = ((const uint4*)(d_w_hi + (size_t)m * CDIM + c0))[ch];
            sWlo[soff] = ((const uint4*)(d_w_lo + (size_t)m * CDIM + c0))[ch];
        }
        #pragma unroll
        for (int t = 0; t < 4; t++) {
            int idx = tid + t * 256;
            int n = idx & 127, oct = idx >> 7;
            const float* src = xb + (size_t)(c0 + oct * 8) * NDIM + i0 + n;
            float v[8];
            #pragma unroll
            for (int j = 0; j < 8; j++) v[j] = src[(size_t)j * NDIM];
            uint4 hw, lw;
            hw.x = pack_hi2(v[0], v[1]); lw.x = pack_lo2(v[0], v[1]);
            hw.y = pack_hi2(v[2], v[3]); lw.y = pack_lo2(v[2], v[3]);
            hw.z = pack_hi2(v[4], v[5]); lw.z = pack_lo2(v[4], v[5]);
            hw.w = pack_hi2(v[6], v[7]); lw.w = pack_lo2(v[6], v[7]);
            int soff = n * 8 + (oct ^ (n & 7));
            sXhi[soff] = hw;
            sXlo[soff] = lw;
        }
        __syncthreads();

        uint32_t tA = smem_base, tAlo = smem_base + 16384;
        uint32_t tB = smem_base + 32768, tBlo = smem_base + 49152;
        #pragma unroll
        for (int ks = 0; ks < 4; ks++) {
            int kc = ks * 2;
            uint32_t ahi[4][4], alo[4][4], bhi[4][2], blo[4][2];
            #pragma unroll
            for (int mf = 0; mf < 4; mf++) ldA(tA, wm * 64 + mf * 16, kc, lane, ahi[mf]);
            ldB4(tB, wn * 32,      kc, lane, &bhi[0][0]);
            ldB4(tB, wn * 32 + 16, kc, lane, &bhi[2][0]);
            #pragma unroll
            for (int mf = 0; mf < 4; mf++)
                #pragma unroll
                for (int nf = 0; nf < 4; nf++) mma_bf16(acc[mf][nf], ahi[mf], bhi[nf]);
            #pragma unroll
            for (int mf = 0; mf < 4; mf++) ldA(tAlo, wm * 64 + mf * 16, kc, lane, alo[mf]);
            #pragma unroll
            for (int mf = 0; mf < 4; mf++)
                #pragma unroll
                for (int nf = 0; nf < 4; nf++) mma_bf16(acc[mf][nf], alo[mf], bhi[nf]);
            ldB4(tBlo, wn * 32,      kc, lane, &blo[0][0]);
            ldB4(tBlo, wn * 32 + 16, kc, lane, &blo[2][0]);
            #pragma unroll
            for (int mf = 0; mf < 4; mf++)
                #pragma unroll
                for (int nf = 0; nf < 4; nf++) mma_bf16(acc[mf][nf], ahi[mf], blo[nf]);
        }
        __syncthreads();
    }

    #pragma unroll
    for (int mf = 0; mf < 4; mf++)
        #pragma unroll
        for (int nf = 0; nf < 4; nf++) {
            int r = wm * 64 + mf * 16 + (lane >> 2);
            int cc = wn * 32 + nf * 8 + (lane & 3) * 2;
            S[r * 132 + cc]           = acc[mf][nf][0];
            S[r * 132 + cc + 1]       = acc[mf][nf][1];
            S[(r + 8) * 132 + cc]     = acc[mf][nf][2];
            S[(r + 8) * 132 + cc + 1] = acc[mf][nf][3];
        }
    __syncthreads();

    // write split bf16 PRE-SWIZZLED: chunk index XORed with (row & 7)
    int arr = lane >> 3, chunk = lane & 7;
    int mbase = (arr >= 2 ? 64 : 0) + chunk * 8;
    __nv_bfloat16* dst = (arr == 0) ? d_fa_hi : (arr == 1) ? d_fa_lo
                       : (arr == 2) ? d_gb_hi : d_gb_lo;
    bool lo_arr = (arr & 1);
    for (int r = wid; r < 128; r += 8) {
        uint4 wv;
        float v0, v1;
        v0 = S[(mbase + 0) * 132 + r]; v1 = S[(mbase + 1) * 132 + r];
        wv.x = lo_arr ? pack_lo2(v0, v1) : pack_hi2(v0, v1);
        v0 = S[(mbase + 2) * 132 + r]; v1 = S[(mbase + 3) * 132 + r];
        wv.y = lo_arr ? pack_lo2(v0, v1) : pack_hi2(v0, v1);
        v0 = S[(mbase + 4) * 132 + r]; v1 = S[(mbase + 5) * 132 + r];
        wv.z = lo_arr ? pack_lo2(v0, v1) : pack_hi2(v0, v1);
        v0 = S[(mbase + 6) * 132 + r]; v1 = S[(mbase + 7) * 132 + r];
        wv.w = lo_arr ? pack_lo2(v0, v1) : pack_hi2(v0, v1);
        int chs = chunk ^ (r & 7);
        *(uint4*)(dst + ((size_t)b * NDIM + i0 + r) * KDIM + chs * 8) = wv;
    }
}

// ---------------- attention passes (split, fine-grained grids) ----------------
// grid (32,32,BATCH) = (jtile, itile, b); tile 128(i) x 128(j); 256 threads.
// Operands loaded via 4 bulk copies (arrays pre-swizzled).  Register epilogues.
// PASS 1: Z[b,j] += sum_i 2^s.  PASS 2: beta = 2^s/Z, rowsum += sum_j beta.
// SMEM: [0,64K) 4 operand tiles; sZ @65536 (512B); mbar @66048.
#define ATTN_SMEM 66176

template <int PASS>
__global__ __launch_bounds__(256, 2) void attn_kernel(float* __restrict__ beta_out) {
    extern __shared__ __align__(1024) char dynsm[];
    uint32_t smem_base = smem_u32(dynsm);
    float* sZ = (float*)(dynsm + 65536);
    const uint32_t MB = smem_base + 66048;

    int b  = blockIdx.z;
    int i0 = blockIdx.y * 128;
    int j0 = blockIdx.x * 128;
    int tid = threadIdx.x;
    int lane = tid & 31, wid = tid >> 5;
    int wm = wid >> 2, wn = wid & 3;

    if (tid == 0) {
        MBARRIER_INIT(MB, 1);
        FENCE_PROXY_ASYNC();
        MBARRIER_EXPECT_TX(MB, 65536);
        CP_BULK(smem_base,         (const char*)(d_fa_hi + ((size_t)b * NDIM + i0) * KDIM),
                16384, MB);
        CP_BULK(smem_base + 16384, (const char*)(d_fa_lo + ((size_t)b * NDIM + i0) * KDIM),
                16384, MB);
        CP_BULK(smem_base + 32768, (const char*)(d_gb_hi + ((size_t)b * NDIM + j0) * KDIM),
                16384, MB);
        CP_BULK(smem_base + 49152, (const char*)(d_gb_lo + ((size_t)b * NDIM + j0) * KDIM),
                16384, MB);
    }
    if (PASS == 2 && tid < 128)
        sZ[tid] = 1.0f / d_Z[b * NDIM + j0 + tid];
    __syncthreads();
    mbar_wait_parity(MB, 0);

    float acc[4][4][4];
    #pragma unroll
    for (int mf = 0; mf < 4; mf++)
        #pragma unroll
        for (int nf = 0; nf < 4; nf++)
            #pragma unroll
            for (int e = 0; e < 4; e++) acc[mf][nf][e] = 0.f;

    uint32_t tA = smem_base, tAlo = smem_base + 16384;
    uint32_t tB = smem_base + 32768, tBlo = smem_base + 49152;
    #pragma unroll
    for (int ks = 0; ks < 4; ks++) {
        int kc = ks * 2;
        uint32_t ahi[4][4], alo[4][4], bhi[4][2], blo[4][2];
        #pragma unroll
        for (int mf = 0; mf < 4; mf++) ldA(tA, wm * 64 + mf * 16, kc, lane, ahi[mf]);
        ldB4(tB, wn * 32,      kc, lane, &bhi[0][0]);
        ldB4(tB, wn * 32 + 16, kc, lane, &bhi[2][0]);
        #pragma unroll
        for (int mf = 0; mf < 4; mf++)
            #pragma unroll
            for (int nf = 0; nf < 4; nf++) mma_bf16(acc[mf][nf], ahi[mf], bhi[nf]);
        #pragma unroll
        for (int mf = 0; mf < 4; mf++) ldA(tAlo, wm * 64 + mf * 16, kc, lane, alo[mf]);
        #pragma unroll
        for (int mf = 0; mf < 4; mf++)
            #pragma unroll
            for (int nf = 0; nf < 4; nf++) mma_bf16(acc[mf][nf], alo[mf], bhi[nf]);
        ldB4(tBlo, wn * 32,      kc, lane, &blo[0][0]);
        ldB4(tBlo, wn * 32 + 16, kc, lane, &blo[2][0]);
        #pragma unroll
        for (int mf = 0; mf < 4; mf++)
            #pragma unroll
            for (int nf = 0; nf < 4; nf++) mma_bf16(acc[mf][nf], ahi[mf], blo[nf]);
    }

    // -------- register-resident epilogue --------
    if (PASS == 1) {
        #pragma unroll
        for (int nf = 0; nf < 4; nf++) {
            float s0 = 0.f, s1 = 0.f;
            #pragma unroll
            for (int mf = 0; mf < 4; mf++) {
                s0 += fast_exp2(acc[mf][nf][0]) + fast_exp2(acc[mf][nf][2]);
                s1 += fast_exp2(acc[mf][nf][1]) + fast_exp2(acc[mf][nf][3]);
            }
            #pragma unroll
            for (int o = 4; o < 32; o <<= 1) {
                s0 += __shfl_xor_sync(0xFFFFFFFFu, s0, o);
                s1 += __shfl_xor_sync(0xFFFFFFFFu, s1, o);
            }
            if (lane < 4) {
                int cc = wn * 32 + nf * 8 + lane * 2;
                atomicAdd(&d_Z[b * NDIM + j0 + cc], s0);
                atomicAdd(&d_Z[b * NDIM + j0 + cc + 1], s1);
            }
        }
    } else {
        float rs0[4], rs1[4];
        #pragma unroll
        for (int mf = 0; mf < 4; mf++) { rs0[mf] = 0.f; rs1[mf] = 0.f; }
        float* ob = beta_out + (size_t)b * NN;
        #pragma unroll
        for (int mf = 0; mf < 4; mf++) {
            int r = wm * 64 + mf * 16 + (lane >> 2);
            #pragma unroll
            for (int nf = 0; nf < 4; nf++) {
                int cc = wn * 32 + nf * 8 + (lane & 3) * 2;
                float iz0 = sZ[cc], iz1 = sZ[cc + 1];
                float v0 = fast_exp2(acc[mf][nf][0]) * iz0;
                float v1 = fast_exp2(acc[mf][nf][1]) * iz1;
                float v2 = fast_exp2(acc[mf][nf][2]) * iz0;
                float v3 = fast_exp2(acc[mf][nf][3]) * iz1;
                __stcs((float2*)(ob + (size_t)(i0 + r) * NDIM + j0 + cc),
                       make_float2(v0, v1));
                __stcs((float2*)(ob + (size_t)(i0 + r + 8) * NDIM + j0 + cc),
                       make_float2(v2, v3));
                rs0[mf] += v0 + v1;
                rs1[mf] += v2 + v3;
            }
        }
        #pragma unroll
        for (int mf = 0; mf < 4; mf++) {
            #pragma unroll
            for (int o = 1; o < 4; o <<= 1) {
                rs0[mf] += __shfl_xor_sync(0xFFFFFFFFu, rs0[mf], o);
                rs1[mf] += __shfl_xor_sync(0xFFFFFFFFu, rs1[mf], o);
            }
        }
        if ((lane & 3) == 0) {
            #pragma unroll
            for (int mf = 0; mf < 4; mf++) {
                int r = wm * 64 + mf * 16 + (lane >> 2);
                atomicAdd(&d_rowsum[b * NDIM + i0 + r], rs0[mf]);
                atomicAdd(&d_rowsum[b * NDIM + i0 + r + 8], rs1[mf]);
            }
        }
    }
}

// ---------------- pooled epilogue ----------------
__global__ __launch_bounds__(256) void pool1_kernel(const float* __restrict__ x) {
    int b = blockIdx.y;
    int cc = blockIdx.x * 8 + (threadIdx.x >> 5);
    int lane = threadIdx.x & 31;
    const float4* xr = (const float4*)(x + ((size_t)b * CDIM + cc) * NDIM);
    const float4* rs = (const float4*)(d_rowsum + b * NDIM);
    float ay = 0.f, ax = 0.f;
    #pragma unroll 8
    for (int i = lane; i < NDIM / 4; i += 32) {
        float4 xv = xr[i];
        float4 rv = rs[i];
        ay += xv.x * rv.x + xv.y * rv.y + xv.z * rv.z + xv.w * rv.w;
        ax += xv.x + xv.y + xv.z + xv.w;
    }
    ay = warp_sum(ay); ax = warp_sum(ax);
    if (lane == 0) {
        d_y[b * CDIM + cc]    = ay * (1.0f / NDIM);
        d_xbar[b * CDIM + cc] = ax * (1.0f / NDIM);
    }
}

__global__ __launch_bounds__(256) void pool2_kernel(const float* __restrict__ Wv,
                                                    const float* __restrict__ gamma,
                                                    float* __restrict__ out) {
    int b = blockIdx.y;
    int c = blockIdx.x * 8 + (threadIdx.x >> 5);
    int lane = threadIdx.x & 31;
    const float* wr = Wv + (size_t)c * CDIM;
    const float* yb = d_y + b * CDIM;
    float a = 0.f;
    for (int k = lane; k < CDIM; k += 32) a += wr[k] * yb[k];
    a = warp_sum(a);
    if (lane == 0) out[b * CDIM + c] = gamma[0] * a + d_xbar[b * CDIM + c];
}

// ---------------- launch ----------------
extern "C" void kernel_launch(void* const* d_in, const int* in_sizes, int n_in,
                              void* d_out, int out_size) {
    const float* x     = (const float*)d_in[0];
    const float* Wq    = (const float*)d_in[1];
    const float* Wk    = (const float*)d_in[2];
    const float* Wv    = (const float*)d_in[3];
    const float* gamma = (const float*)d_in[4];
    float* out    = (float*)d_out;
    float* pooled = out;                 // [B,C,1,1] = 2048 floats
    float* beta   = out + BATCH * CDIM;  // [B,N,N]

    cudaFuncSetAttribute(fg_kernel, cudaFuncAttributeMaxDynamicSharedMemorySize, FG_SMEM);
    cudaFuncSetAttribute(attn_kernel<1>, cudaFuncAttributeMaxDynamicSharedMemorySize,
                         ATTN_SMEM);
    cudaFuncSetAttribute(attn_kernel<2>, cudaFuncAttributeMaxDynamicSharedMemorySize,
                         ATTN_SMEM);

    wsplit_kernel<<<(128 * CDIM + 255) / 256, 256>>>(Wq, Wk);
    fg_kernel<<<dim3(32, BATCH), 256, FG_SMEM>>>(x);
    attn_kernel<1><<<dim3(32, 32, BATCH), 256, ATTN_SMEM>>>(beta);
    attn_kernel<2><<<dim3(32, 32, BATCH), 256, ATTN_SMEM>>>(beta);
    pool1_kernel<<<dim3(CDIM / 8, BATCH), 256>>>(x);
    pool2_kernel<<<dim3(CDIM / 8, BATCH), 256>>>(Wv, gamma, pooled);
}